// round 14
// baseline (speedup 1.0000x reference)
#include <cuda_runtime.h>
#include <math.h>

// ---------------- problem constants ----------------
#define M_TOT 131072
#define HEADS 4

// ---------------- scratch ----------------
__device__ unsigned g_qkv [(size_t)M_TOT * 192];  // packed bf16x2: Q|K|V words
__device__ float g_xln [(size_t)M_TOT * 128];
__device__ float g_xres[(size_t)M_TOT * 128];
__device__ float g_ps  [256 * 4 * 4096];          // rpb+mask, C-frag order
__device__ unsigned g_wtf[98304];  // qkv bf16(rm) | proj bf16(frag) | fc1 bf16 | fc2 bf16

__device__ __forceinline__ int perm_row(int r) {
    int b_ = r >> 7, tt = r & 127;
    int b = b_ >> 8, w = b_ & 255;
    int wh = w >> 4, ww = w & 15;
    int t = tt >> 6, n = tt & 63;
    int i = n >> 3, j = n & 7;
    int oh = (wh * 8 + i + 4) & 127;
    int ow = (ww * 8 + j + 4) & 127;
    return (b * 2 + t) * 16384 + oh * 128 + ow;
}

__device__ __forceinline__ unsigned f2tf(float f) {
    unsigned u;
    asm("cvt.rna.tf32.f32 %0, %1;" : "=r"(u) : "f"(f));
    return u;
}
__device__ __forceinline__ float round_tf(float f) { return __uint_as_float(f2tf(f)); }

__device__ __forceinline__ unsigned pack_bf(float lo, float hi) {
    unsigned d;
    asm("cvt.rn.bf16x2.f32 %0, %1, %2;" : "=r"(d) : "f"(hi), "f"(lo));
    return d;
}

#define MMA_BF16(d, a0, a1, a2, a3, b0, b1)                                            \
    asm volatile(                                                                      \
        "mma.sync.aligned.m16n8k16.row.col.f32.bf16.bf16.f32 "                         \
        "{%0,%1,%2,%3},{%4,%5,%6,%7},{%8,%9},{%0,%1,%2,%3};"                           \
        : "+f"(d[0]), "+f"(d[1]), "+f"(d[2]), "+f"(d[3])                               \
        : "r"(a0), "r"(a1), "r"(a2), "r"(a3), "r"(b0), "r"(b1))

// ---------------- setup: weight conversion + rpb/mask table (merged) ----------------
__global__ void setup_kernel(const float* __restrict__ qkv_w, const float* __restrict__ proj_w,
                             const float* __restrict__ fc1_w, const float* __restrict__ fc2_w,
                             const float* __restrict__ rpb,
                             unsigned* __restrict__ wtf, float* __restrict__ ps) {
    int bid = blockIdx.x;
    int tid = threadIdx.x;
    if (bid < 384) {
        int i = bid * 256 + tid;
        if (i < 24576) {             // qkv: [384][64 words]
            int n = i >> 6, w = i & 63;
            wtf[i] = pack_bf(qkv_w[n * 128 + 2 * w], qkv_w[n * 128 + 2 * w + 1]);
        } else if (i < 32768) {      // proj B-frag
            int j = i - 24576;
            int half = j & 1, pos = j >> 1;
            int lane = pos & 31, kc = (pos >> 5) & 7, n8 = pos >> 8;
            int g = lane >> 2, t = lane & 3;
            int n = n8 * 8 + g;
            int kb = 16 * kc + (half ? 8 : 0) + 2 * t;
            wtf[i] = pack_bf(proj_w[n * 128 + kb], proj_w[n * 128 + kb + 1]);
        } else if (i < 65536) {      // fc1
            int j = i - 32768;
            int n = j >> 6, w = j & 63;
            wtf[i] = pack_bf(fc1_w[n * 128 + 2 * w], fc1_w[n * 128 + 2 * w + 1]);
        } else {                     // fc2
            int j = i - 65536;
            int n = j >> 8, w = j & 255;
            wtf[i] = pack_bf(fc2_w[n * 512 + 2 * w], fc2_w[n * 512 + 2 * w + 1]);
        }
        return;
    }
    // ps table: blocks 384..1407 -> (wwin, head)
    int pb = bid - 384;
    int wwin = pb >> 2, head = pb & 3;
    int wh = wwin >> 4, ww = wwin & 15;
    float* dst = ps + (size_t)(wwin * 4 + head) * 4096;
#pragma unroll
    for (int it = 0; it < 16; it++) {
        int e = tid + it * 256;
        int qn = e >> 6, kn = e & 63;
        int qi2 = qn >> 3, qj = qn & 7, ki = kn >> 3, kj = kn & 7;
        int rel = (qi2 - ki + 7) * 15 + (qj - kj + 7);
        float v = rpb[rel * HEADS + head];
        int gqh = wh * 8 + qi2, gqw = ww * 8 + qj;
        int gkh = wh * 8 + ki,  gkw = ww * 8 + kj;
        int rq = (gqh < 120 ? 0 : (gqh < 124 ? 1 : 2)) * 3 + (gqw < 120 ? 0 : (gqw < 124 ? 1 : 2));
        int rk = (gkh < 120 ? 0 : (gkh < 124 ? 1 : 2)) * 3 + (gkw < 120 ? 0 : (gkw < 124 ? 1 : 2));
        if (rq != rk) v -= 100.0f;
        int qtile = qn >> 4, ntile = kn >> 3;
        int ln = (qn & 7) * 4 + ((kn & 7) >> 1);
        int reg = ((qn >> 3) & 1) * 2 + (kn & 1);
        dst[((qtile * 8 + ntile) * 32 + ln) * 4 + reg] = v;
    }
}

// ---------------- qkv GEMM (bf16): A staged once, weights streamed ----------------
#define QKV_SMEM ((8448 + 8448) * 4)
__global__ __launch_bounds__(512) void qkv_kernel(
    const float* __restrict__ xv, const unsigned* __restrict__ Wq_,
    const float* __restrict__ bias, unsigned* __restrict__ out) {
    extern __shared__ unsigned sm[];
    unsigned* XA = sm;
    unsigned* WB = sm + 8448;

    const uint4* Wg = reinterpret_cast<const uint4*>(Wq_);
    const int tid = threadIdx.x;
    const int lane = tid & 31;
    const int wid = tid >> 5;
    const int wm = wid >> 2, wn = wid & 3;
    const int g = lane >> 2, t = lane & 3;
    const int bm = blockIdx.x * 128;
    const float scale = 0.17677669529663687f;

#pragma unroll
    for (int it = 0; it < 8; it++) {
        int c = tid + it * 512;
        int row = c >> 5, kq = c & 31;
        int src = perm_row(bm + row);
        float4 v = *reinterpret_cast<const float4*>(xv + (size_t)src * 128 + kq * 4);
        int rg = ((row >> 4) * 2 + ((row >> 3) & 1)) * 528 + (row & 7) * 8;
        int w0 = 2 * kq, w1 = 2 * kq + 1;
        XA[rg + (w0 >> 3) * 66 + ((w0 >> 2) & 1) + 2 * (w0 & 3)] = pack_bf(v.x, v.y);
        XA[rg + (w1 >> 3) * 66 + ((w1 >> 2) & 1) + 2 * (w1 & 3)] = pack_bf(v.z, v.w);
    }

    int wsrc[2], wst[2];
#pragma unroll
    for (int it = 0; it < 2; it++) {
        int e = tid + it * 512;
        int n = e >> 4, wq = e & 15;
        wsrc[it] = n * 16 + wq;
        wst[it] = (n >> 3) * 528 + (wq >> 1) * 66 + (n & 7) * 8 + (wq & 1);
    }
    {
        uint4 v[2];
#pragma unroll
        for (int it = 0; it < 2; it++) v[it] = Wg[wsrc[it]];
#pragma unroll
        for (int it = 0; it < 2; it++) {
            WB[wst[it] + 0] = v[it].x; WB[wst[it] + 2] = v[it].y;
            WB[wst[it] + 4] = v[it].z; WB[wst[it] + 6] = v[it].w;
        }
    }
    __syncthreads();

    int p = 0;
    for (int c = 0; c < 6; c++) {
        uint4 wv[2];
        if (c < 5) {
#pragma unroll
            for (int it = 0; it < 2; it++) wv[it] = Wg[wsrc[it] + (c + 1) * 1024];
        }
        unsigned* Wp = WB + p * 4224;

        float accs[2][2][4];
#pragma unroll
        for (int mi = 0; mi < 2; mi++)
#pragma unroll
            for (int ni = 0; ni < 2; ni++)
#pragma unroll
                for (int q = 0; q < 4; q++) accs[mi][ni][q] = 0.f;

#pragma unroll
        for (int k16 = 0; k16 < 8; k16++) {
            unsigned a[2][4], b[2][2];
#pragma unroll
            for (int mi = 0; mi < 2; mi++) {
                int base = ((wm * 2 + mi) * 2) * 528 + k16 * 66 + lane * 2;
                uint2 q0 = *reinterpret_cast<const uint2*>(&XA[base]);
                uint2 q1 = *reinterpret_cast<const uint2*>(&XA[base + 528]);
                a[mi][0] = q0.x; a[mi][2] = q0.y;
                a[mi][1] = q1.x; a[mi][3] = q1.y;
            }
#pragma unroll
            for (int ni = 0; ni < 2; ni++) {
                uint2 q = *reinterpret_cast<const uint2*>(&Wp[(wn * 2 + ni) * 528 + k16 * 66 + lane * 2]);
                b[ni][0] = q.x; b[ni][1] = q.y;
            }
#pragma unroll
            for (int mi = 0; mi < 2; mi++)
#pragma unroll
                for (int ni = 0; ni < 2; ni++)
                    MMA_BF16(accs[mi][ni], a[mi][0], a[mi][1], a[mi][2], a[mi][3],
                             b[ni][0], b[ni][1]);
        }

        float sc = (c < 2) ? scale : 1.0f;
#pragma unroll
        for (int mi = 0; mi < 2; mi++) {
#pragma unroll
            for (int rh = 0; rh < 2; rh++) {
                int r = bm + wm * 32 + mi * 16 + g + rh * 8;
#pragma unroll
                for (int ni = 0; ni < 2; ni++) {
                    int cw = c * 32 + wn * 8 + ni * 4 + t;
                    int col = 2 * cw;
                    out[(size_t)r * 192 + cw] =
                        pack_bf((accs[mi][ni][rh * 2 + 0] + bias[col]) * sc,
                                (accs[mi][ni][rh * 2 + 1] + bias[col + 1]) * sc);
                }
            }
        }

        if (c < 5) {
            unsigned* Wn = WB + (p ^ 1) * 4224;
#pragma unroll
            for (int it = 0; it < 2; it++) {
                Wn[wst[it] + 0] = wv[it].x; Wn[wst[it] + 2] = wv[it].y;
                Wn[wst[it] + 4] = wv[it].z; Wn[wst[it] + 6] = wv[it].w;
            }
            p ^= 1;
        }
        __syncthreads();
    }
}

// ---------------- fused attention + proj + scatter + residual + LN2 (all bf16) ----------------
// smem words: OA 0..8448 | QA 8448..10560 | KB 10560..12672 | VB 12672..14784
#define AP_OA 0
#define AP_QA 8448
#define AP_KB 10560
#define AP_VB 12672
#define AP_SMEM (14784 * 4)

__global__ __launch_bounds__(256) void attnproj_kernel(
    const unsigned* __restrict__ qkv, const float* __restrict__ ps,
    const unsigned* __restrict__ Wp_, const float* __restrict__ bias,
    const float* __restrict__ res, float* __restrict__ xres, float* __restrict__ xln,
    const float* __restrict__ gw, const float* __restrict__ bw) {
    extern __shared__ unsigned sm[];
    unsigned* OA = sm + AP_OA;
    unsigned* QA = sm + AP_QA;
    unsigned* KB = sm + AP_KB;
    unsigned* VB = sm + AP_VB;
    __shared__ float smS[128][2], smQ[128][2];

    const int win = blockIdx.x;
    const int tid = threadIdx.x;
    const int lane = tid & 31, w = tid >> 5;
    const int g = lane >> 2, t = lane & 3;
    const int qtile = w & 3;
    const float* psW = ps + (size_t)((win & 255) * 4) * 4096;
    const uint4* qkv4 = reinterpret_cast<const uint4*>(qkv);

    for (int head = 0; head < HEADS; head++) {
        // ---- stage Q (A layout), K (B layout) ----
#pragma unroll
        for (int it = 0; it < 2; it++) {
            int e = tid + it * 256;
            int row = e >> 2, q4 = e & 3;
            size_t idx = ((size_t)(win * 128 + row)) * 48 + head * 4 + q4;
            uint4 qv = qkv4[idx];
            uint4 kv = qkv4[idx + 16];
            int rgq = ((row >> 4) * 2 + ((row >> 3) & 1)) * 132 + (row & 7) * 8;
            int rgk = (row >> 3) * 132 + (row & 7) * 8;
            unsigned qw[4] = {qv.x, qv.y, qv.z, qv.w};
            unsigned kw[4] = {kv.x, kv.y, kv.z, kv.w};
#pragma unroll
            for (int j = 0; j < 4; j++) {
                int wd = q4 * 4 + j;
                int off = (wd >> 3) * 66 + ((wd >> 2) & 1) + 2 * (wd & 3);
                QA[rgq + off] = qw[j];
                KB[rgk + off] = kw[j];
            }
        }
        // ---- stage V: repack dim-pairs -> token-pairs ----
        {
            int e = tid;
            int tp = e >> 2, q4 = e & 3;
            size_t idxe = ((size_t)(win * 128 + 2 * tp)) * 48 + head * 4 + 32 + q4;
            uint4 ve = qkv4[idxe];
            uint4 vo = qkv4[idxe + 48];
            int kc = tp >> 3, kw2 = tp & 7;
            int off = (kw2 & 3) * 2 + (kw2 >> 2);
            unsigned ew[4] = {ve.x, ve.y, ve.z, ve.w};
            unsigned ow[4] = {vo.x, vo.y, vo.z, vo.w};
#pragma unroll
            for (int j = 0; j < 4; j++) {
                int wd = q4 * 4 + j;
                unsigned d0 = __byte_perm(ew[j], ow[j], 0x5410);
                unsigned d1 = __byte_perm(ew[j], ow[j], 0x7632);
                int n0 = 2 * wd, n1 = 2 * wd + 1;
                VB[(n0 >> 3) * 528 + kc * 66 + (n0 & 7) * 8 + off] = d0;
                VB[(n1 >> 3) * 528 + kc * 66 + (n1 & 7) * 8 + off] = d1;
            }
        }
        __syncthreads();

        // ---- S = Q @ K^T ----
        float acc[16][4];
#pragma unroll
        for (int nt = 0; nt < 16; nt++)
#pragma unroll
            for (int i = 0; i < 4; i++) acc[nt][i] = 0.f;

#pragma unroll
        for (int k16 = 0; k16 < 2; k16++) {
            int abase = (w * 2) * 132 + k16 * 66 + lane * 2;
            uint2 q0 = *reinterpret_cast<const uint2*>(&QA[abase]);
            uint2 q1 = *reinterpret_cast<const uint2*>(&QA[abase + 132]);
#pragma unroll
            for (int nt = 0; nt < 16; nt++) {
                uint2 b = *reinterpret_cast<const uint2*>(&KB[nt * 132 + k16 * 66 + lane * 2]);
                MMA_BF16(acc[nt], q0.x, q1.x, q0.y, q1.y, b.x, b.y);
            }
        }

        // ---- + rpb/mask, softmax ----
        const float* psh = psW + head * 4096;
        float m0 = -1e30f, m1 = -1e30f;
#pragma unroll
        for (int nt = 0; nt < 16; nt++) {
            float4 p = *reinterpret_cast<const float4*>(psh + ((qtile * 8 + (nt & 7)) * 32 + lane) * 4);
            acc[nt][0] += p.x; acc[nt][1] += p.y;
            acc[nt][2] += p.z; acc[nt][3] += p.w;
            m0 = fmaxf(m0, fmaxf(acc[nt][0], acc[nt][1]));
            m1 = fmaxf(m1, fmaxf(acc[nt][2], acc[nt][3]));
        }
        m0 = fmaxf(m0, __shfl_xor_sync(0xffffffffu, m0, 1));
        m0 = fmaxf(m0, __shfl_xor_sync(0xffffffffu, m0, 2));
        m1 = fmaxf(m1, __shfl_xor_sync(0xffffffffu, m1, 1));
        m1 = fmaxf(m1, __shfl_xor_sync(0xffffffffu, m1, 2));

        float l0 = 0.f, l1 = 0.f;
#pragma unroll
        for (int nt = 0; nt < 16; nt++) {
            acc[nt][0] = __expf(acc[nt][0] - m0);
            acc[nt][1] = __expf(acc[nt][1] - m0);
            acc[nt][2] = __expf(acc[nt][2] - m1);
            acc[nt][3] = __expf(acc[nt][3] - m1);
            l0 += acc[nt][0] + acc[nt][1];
            l1 += acc[nt][2] + acc[nt][3];
        }
        l0 += __shfl_xor_sync(0xffffffffu, l0, 1);
        l0 += __shfl_xor_sync(0xffffffffu, l0, 2);
        l1 += __shfl_xor_sync(0xffffffffu, l1, 1);
        l1 += __shfl_xor_sync(0xffffffffu, l1, 2);
        float inv0 = 1.0f / l0, inv1 = 1.0f / l1;

        // ---- O = P @ V ----
        float oacc[4][4];
#pragma unroll
        for (int n8 = 0; n8 < 4; n8++)
#pragma unroll
            for (int i = 0; i < 4; i++) oacc[n8][i] = 0.f;

#pragma unroll
        for (int kc = 0; kc < 8; kc++) {
            unsigned a0 = pack_bf(acc[2 * kc][0], acc[2 * kc][1]);
            unsigned a1 = pack_bf(acc[2 * kc][2], acc[2 * kc][3]);
            unsigned a2 = pack_bf(acc[2 * kc + 1][0], acc[2 * kc + 1][1]);
            unsigned a3 = pack_bf(acc[2 * kc + 1][2], acc[2 * kc + 1][3]);
#pragma unroll
            for (int n8 = 0; n8 < 4; n8++) {
                uint2 b = *reinterpret_cast<const uint2*>(&VB[n8 * 528 + kc * 66 + lane * 2]);
                MMA_BF16(oacc[n8], a0, a1, a2, a3, b.x, b.y);
            }
        }

        // ---- write O (packed bf16x2) into OA in proj A-frag word layout ----
        {
            int rg0 = (w * 2) * 528 + g * 8;       // row = w*16 + g
            int rg1 = (w * 2 + 1) * 528 + g * 8;   // row = w*16 + g + 8
#pragma unroll
            for (int n8 = 0; n8 < 4; n8++) {
                int cw = head * 16 + n8 * 4 + t;
                int off = (cw >> 3) * 66 + ((cw >> 2) & 1) + 2 * (cw & 3);
                OA[rg0 + off] = pack_bf(oacc[n8][0] * inv0, oacc[n8][1] * inv0);
                OA[rg1 + off] = pack_bf(oacc[n8][2] * inv1, oacc[n8][3] * inv1);
            }
        }
        __syncthreads();
    }

    // ---- proj: C(128x128) = OA @ Wp^T (bf16) ----
    const uint2* Wp2 = reinterpret_cast<const uint2*>(Wp_);
    const int wm = w >> 1, wn = w & 1;
    float acc2[2][8][4];
#pragma unroll
    for (int mi = 0; mi < 2; mi++)
#pragma unroll
        for (int ni = 0; ni < 8; ni++)
#pragma unroll
            for (int q = 0; q < 4; q++) acc2[mi][ni][q] = 0.f;

#pragma unroll
    for (int k16 = 0; k16 < 8; k16++) {
        unsigned a[2][4];
#pragma unroll
        for (int mi = 0; mi < 2; mi++) {
            int base = ((wm * 2 + mi) * 2) * 528 + k16 * 66 + lane * 2;
            uint2 q0 = *reinterpret_cast<const uint2*>(&OA[base]);
            uint2 q1 = *reinterpret_cast<const uint2*>(&OA[base + 528]);
            a[mi][0] = q0.x; a[mi][2] = q0.y;
            a[mi][1] = q1.x; a[mi][3] = q1.y;
        }
#pragma unroll
        for (int ni = 0; ni < 8; ni++) {
            uint2 b = Wp2[((wn * 8 + ni) * 8 + k16) * 32 + lane];
#pragma unroll
            for (int mi = 0; mi < 2; mi++)
                MMA_BF16(acc2[mi][ni], a[mi][0], a[mi][1], a[mi][2], a[mi][3], b.x, b.y);
        }
    }

    // ---- epilogue: bias + residual (scatter) + LN2 ----
#pragma unroll
    for (int mi = 0; mi < 2; mi++) {
#pragma unroll
        for (int rh = 0; rh < 2; rh++) {
            int lrow = wm * 32 + mi * 16 + g + rh * 8;
            int xrow = perm_row(win * 128 + lrow);
            float v[16];
            float s = 0.f, q = 0.f;
#pragma unroll
            for (int ni = 0; ni < 8; ni++) {
                int cc = wn * 64 + ni * 8 + t * 2;
                float2 rr = *reinterpret_cast<const float2*>(res + (size_t)xrow * 128 + cc);
                float x0 = acc2[mi][ni][rh * 2 + 0] + bias[cc] + rr.x;
                float x1 = acc2[mi][ni][rh * 2 + 1] + bias[cc + 1] + rr.y;
                *reinterpret_cast<float2*>(xres + (size_t)xrow * 128 + cc) = make_float2(x0, x1);
                v[ni * 2 + 0] = x0; v[ni * 2 + 1] = x1;
                s += x0 + x1; q += x0 * x0 + x1 * x1;
            }
            s += __shfl_xor_sync(0xffffffffu, s, 1);
            s += __shfl_xor_sync(0xffffffffu, s, 2);
            q += __shfl_xor_sync(0xffffffffu, q, 1);
            q += __shfl_xor_sync(0xffffffffu, q, 2);
            if (t == 0) { smS[lrow][wn] = s; smQ[lrow][wn] = q; }
            __syncthreads();
            float S = smS[lrow][0] + smS[lrow][1];
            float Q = smQ[lrow][0] + smQ[lrow][1];
            float mu = S * (1.f / 128.f);
            float var = Q * (1.f / 128.f) - mu * mu;
            float rs = rsqrtf(var + 1e-5f);
#pragma unroll
            for (int ni = 0; ni < 8; ni++) {
                int cc = wn * 64 + ni * 8 + t * 2;
                float2 o;
                o.x = round_tf((v[ni * 2 + 0] - mu) * rs * gw[cc] + bw[cc]);
                o.y = round_tf((v[ni * 2 + 1] - mu) * rs * gw[cc + 1] + bw[cc + 1]);
                *reinterpret_cast<float2*>(xln + (size_t)xrow * 128 + cc) = o;
            }
        }
    }
}

// ---------------- fused MLP (bf16): fc1 + gelu + fc2 + residual + LN1 (unchanged) ----------------
#define MLP_SMEM (21120 * 4)
__global__ __launch_bounds__(512) void mlp_kernel(
    const float* __restrict__ xln, const unsigned* __restrict__ W1g4_,
    const unsigned* __restrict__ W2g4_,
    const float* __restrict__ b1, const float* __restrict__ b2,
    const float* __restrict__ res, float* __restrict__ out,
    const float* __restrict__ gw, const float* __restrict__ bw) {
    extern __shared__ unsigned sm[];
    unsigned* XA = sm;
    unsigned* W1 = sm + 8448;
    unsigned* W2 = sm + 12672;
    unsigned* HH = sm + 16896;
    __shared__ float smS[128][4], smQ[128][4];

    const uint4* W1g = reinterpret_cast<const uint4*>(W1g4_);
    const uint4* W2g = reinterpret_cast<const uint4*>(W2g4_);

    const int tid = threadIdx.x;
    const int lane = tid & 31;
    const int wid = tid >> 5;
    const int wm = wid >> 2, wn = wid & 3;
    const int g = lane >> 2, t = lane & 3;
    const int bm = blockIdx.x * 128;

#pragma unroll
    for (int it = 0; it < 8; it++) {
        int c = tid + it * 512;
        int row = c >> 5, kq = c & 31;
        float4 v = *reinterpret_cast<const float4*>(xln + (size_t)(bm + row) * 128 + kq * 4);
        int rg = ((row >> 4) * 2 + ((row >> 3) & 1)) * 528 + (row & 7) * 8;
        int w0 = 2 * kq, w1 = 2 * kq + 1;
        XA[rg + (w0 >> 3) * 66 + ((w0 >> 2) & 1) + 2 * (w0 & 3)] = pack_bf(v.x, v.y);
        XA[rg + (w1 >> 3) * 66 + ((w1 >> 2) & 1) + 2 * (w1 & 3)] = pack_bf(v.z, v.w);
    }

    int w1src[2], w1st[2], w2src[2], w2st[2];
#pragma unroll
    for (int it = 0; it < 2; it++) {
        int e = tid + it * 512;
        int n = e >> 4, wq = e & 15;
        w1src[it] = n * 16 + wq;
        w1st[it] = (n >> 3) * 528 + (wq >> 1) * 66 + (n & 7) * 8 + (wq & 1);
        int n2 = e >> 3, wq2 = e & 7;
        w2src[it] = n2 * 64 + wq2;
        w2st[it] = (n2 >> 3) * 264 + (wq2 >> 1) * 66 + (n2 & 7) * 8 + (wq2 & 1);
    }

    {
        uint4 v[2];
#pragma unroll
        for (int it = 0; it < 2; it++) v[it] = W1g[w1src[it]];
#pragma unroll
        for (int it = 0; it < 2; it++) {
            W1[w1st[it] + 0] = v[it].x; W1[w1st[it] + 2] = v[it].y;
            W1[w1st[it] + 4] = v[it].z; W1[w1st[it] + 6] = v[it].w;
        }
    }
    __syncthreads();

    float acco[2][4][4];
#pragma unroll
    for (int mi = 0; mi < 2; mi++)
#pragma unroll
        for (int ni = 0; ni < 4; ni++)
#pragma unroll
            for (int c = 0; c < 4; c++) acco[mi][ni][c] = 0.f;

    for (int c = 0; c < 8; c++) {
        uint4 w2v[2];
#pragma unroll
        for (int it = 0; it < 2; it++) w2v[it] = W2g[w2src[it] + c * 8];

        float accs[2][2][4];
#pragma unroll
        for (int mi = 0; mi < 2; mi++)
#pragma unroll
            for (int ni = 0; ni < 2; ni++)
#pragma unroll
                for (int q = 0; q < 4; q++) accs[mi][ni][q] = 0.f;
#pragma unroll
        for (int k16 = 0; k16 < 8; k16++) {
            unsigned a[2][4], b[2][2];
#pragma unroll
            for (int mi = 0; mi < 2; mi++) {
                int base = ((wm * 2 + mi) * 2) * 528 + k16 * 66 + lane * 2;
                uint2 q0 = *reinterpret_cast<const uint2*>(&XA[base]);
                uint2 q1 = *reinterpret_cast<const uint2*>(&XA[base + 528]);
                a[mi][0] = q0.x; a[mi][2] = q0.y;
                a[mi][1] = q1.x; a[mi][3] = q1.y;
            }
#pragma unroll
            for (int ni = 0; ni < 2; ni++) {
                uint2 q = *reinterpret_cast<const uint2*>(&W1[(wn * 2 + ni) * 528 + k16 * 66 + lane * 2]);
                b[ni][0] = q.x; b[ni][1] = q.y;
            }
#pragma unroll
            for (int mi = 0; mi < 2; mi++)
#pragma unroll
                for (int ni = 0; ni < 2; ni++)
                    MMA_BF16(accs[mi][ni], a[mi][0], a[mi][1], a[mi][2], a[mi][3],
                             b[ni][0], b[ni][1]);
        }

#pragma unroll
        for (int it = 0; it < 2; it++) {
            W2[w2st[it] + 0] = w2v[it].x; W2[w2st[it] + 2] = w2v[it].y;
            W2[w2st[it] + 4] = w2v[it].z; W2[w2st[it] + 6] = w2v[it].w;
        }

#pragma unroll
        for (int mi = 0; mi < 2; mi++) {
#pragma unroll
            for (int ni = 0; ni < 2; ni++) {
                int kl0 = wn * 16 + ni * 8 + t * 2;
                int ww = kl0 >> 1;
                int wof = (ww >> 3) * 66 + ((ww >> 2) & 1) + 2 * (ww & 3);
                float bb0 = b1[c * 64 + kl0], bb1 = b1[c * 64 + kl0 + 1];
#pragma unroll
                for (int rh = 0; rh < 2; rh++) {
                    float x0 = accs[mi][ni][rh * 2 + 0] + bb0;
                    float x1 = accs[mi][ni][rh * 2 + 1] + bb1;
                    x0 = 0.5f * x0 * (1.0f + erff(x0 * 0.7071067811865475f));
                    x1 = 0.5f * x1 * (1.0f + erff(x1 * 0.7071067811865475f));
                    int addr = ((wm * 2 + mi) * 2 + rh) * 264 + wof + g * 8;
                    HH[addr] = pack_bf(x0, x1);
                }
            }
        }
        __syncthreads();

        uint4 w1v[2];
        if (c < 7) {
#pragma unroll
            for (int it = 0; it < 2; it++) w1v[it] = W1g[w1src[it] + (c + 1) * 1024];
        }

#pragma unroll
        for (int k16 = 0; k16 < 4; k16++) {
            unsigned a[2][4], b[4][2];
#pragma unroll
            for (int mi = 0; mi < 2; mi++) {
                int base = ((wm * 2 + mi) * 2) * 264 + k16 * 66 + lane * 2;
                uint2 q0 = *reinterpret_cast<const uint2*>(&HH[base]);
                uint2 q1 = *reinterpret_cast<const uint2*>(&HH[base + 264]);
                a[mi][0] = q0.x; a[mi][2] = q0.y;
                a[mi][1] = q1.x; a[mi][3] = q1.y;
            }
#pragma unroll
            for (int ni = 0; ni < 4; ni++) {
                uint2 q = *reinterpret_cast<const uint2*>(&W2[(wn * 4 + ni) * 264 + k16 * 66 + lane * 2]);
                b[ni][0] = q.x; b[ni][1] = q.y;
            }
#pragma unroll
            for (int mi = 0; mi < 2; mi++)
#pragma unroll
                for (int ni = 0; ni < 4; ni++)
                    MMA_BF16(acco[mi][ni], a[mi][0], a[mi][1], a[mi][2], a[mi][3],
                             b[ni][0], b[ni][1]);
        }

        if (c < 7) {
#pragma unroll
            for (int it = 0; it < 2; it++) {
                W1[w1st[it] + 0] = w1v[it].x; W1[w1st[it] + 2] = w1v[it].y;
                W1[w1st[it] + 4] = w1v[it].z; W1[w1st[it] + 6] = w1v[it].w;
            }
        }
        __syncthreads();
    }

#pragma unroll
    for (int mi = 0; mi < 2; mi++) {
#pragma unroll
        for (int rh = 0; rh < 2; rh++) {
            int lrow = wm * 32 + mi * 16 + g + rh * 8;
            int r = bm + lrow;
            float v[8];
            float s = 0.f, q = 0.f;
#pragma unroll
            for (int ni = 0; ni < 4; ni++) {
                int cc = wn * 32 + ni * 8 + t * 2;
                float2 rr = *reinterpret_cast<const float2*>(res + (size_t)r * 128 + cc);
                float x0 = acco[mi][ni][rh * 2 + 0] + b2[cc] + rr.x;
                float x1 = acco[mi][ni][rh * 2 + 1] + b2[cc + 1] + rr.y;
                v[ni * 2 + 0] = x0; v[ni * 2 + 1] = x1;
                s += x0 + x1; q += x0 * x0 + x1 * x1;
            }
            s += __shfl_xor_sync(0xffffffffu, s, 1);
            s += __shfl_xor_sync(0xffffffffu, s, 2);
            q += __shfl_xor_sync(0xffffffffu, q, 1);
            q += __shfl_xor_sync(0xffffffffu, q, 2);
            if (t == 0) { smS[lrow][wn] = s; smQ[lrow][wn] = q; }
            __syncthreads();
            float S = smS[lrow][0] + smS[lrow][1] + smS[lrow][2] + smS[lrow][3];
            float Q = smQ[lrow][0] + smQ[lrow][1] + smQ[lrow][2] + smQ[lrow][3];
            float mu = S * (1.f / 128.f);
            float var = Q * (1.f / 128.f) - mu * mu;
            float rs = rsqrtf(var + 1e-5f);
#pragma unroll
            for (int ni = 0; ni < 4; ni++) {
                int cc = wn * 32 + ni * 8 + t * 2;
                float2 o;
                o.x = (v[ni * 2 + 0] - mu) * rs * gw[cc] + bw[cc];
                o.y = (v[ni * 2 + 1] - mu) * rs * gw[cc + 1] + bw[cc + 1];
                *reinterpret_cast<float2*>(out + (size_t)r * 128 + cc) = o;
            }
        }
    }
}

// ---------------- launch ----------------
extern "C" void kernel_launch(void* const* d_in, const int* in_sizes, int n_in,
                              void* d_out, int out_size) {
    const float* x_v    = (const float*)d_in[0];
    const float* qkv_w  = (const float*)d_in[1];
    const float* qkv_b  = (const float*)d_in[2];
    const float* proj_w = (const float*)d_in[3];
    const float* proj_b = (const float*)d_in[4];
    const float* rpb    = (const float*)d_in[5];
    const float* n1w    = (const float*)d_in[6];
    const float* n1b    = (const float*)d_in[7];
    const float* n2w    = (const float*)d_in[8];
    const float* n2b    = (const float*)d_in[9];
    const float* fc1w   = (const float*)d_in[10];
    const float* fc1b   = (const float*)d_in[11];
    const float* fc2w   = (const float*)d_in[12];
    const float* fc2b   = (const float*)d_in[13];
    float* out = (float*)d_out;

    float *xln, *xres, *ps;
    unsigned *qkvb, *wtf;
    cudaGetSymbolAddress((void**)&qkvb, g_qkv);
    cudaGetSymbolAddress((void**)&xln,  g_xln);
    cudaGetSymbolAddress((void**)&xres, g_xres);
    cudaGetSymbolAddress((void**)&ps,   g_ps);
    cudaGetSymbolAddress((void**)&wtf,  g_wtf);

    cudaFuncSetAttribute(qkv_kernel, cudaFuncAttributeMaxDynamicSharedMemorySize, QKV_SMEM);
    cudaFuncSetAttribute(attnproj_kernel, cudaFuncAttributeMaxDynamicSharedMemorySize, AP_SMEM);
    cudaFuncSetAttribute(mlp_kernel, cudaFuncAttributeMaxDynamicSharedMemorySize, MLP_SMEM);

    // 0. setup: weights (bf16 packed) + rpb/mask table in one launch
    setup_kernel<<<1408, 256>>>(qkv_w, proj_w, fc1w, fc2w, rpb, wtf, ps);
    // 1. qkv (bf16) = gather(x_v) @ qkv_w^T + b, packed bf16x2 output
    qkv_kernel<<<1024, 512, QKV_SMEM>>>(x_v, wtf, qkv_b, qkvb);
    // 2. fused attention + proj + scatter + residual + LN2 (all bf16)
    attnproj_kernel<<<1024, 256, AP_SMEM>>>(qkvb, ps, wtf + 24576, proj_b,
                                            x_v, xres, xln, n2w, n2b);
    // 3. fused MLP (bf16) -> final output
    mlp_kernel<<<1024, 512, MLP_SMEM>>>(xln, wtf + 32768, wtf + 65536,
                                        fc1b, fc2b, xres, out, n1w, n1b);
}

// round 15
// speedup vs baseline: 1.0777x; 1.0777x over previous
#include <cuda_runtime.h>
#include <math.h>

// ---------------- problem constants ----------------
#define M_TOT 131072
#define HEADS 4

// ---------------- scratch ----------------
__device__ unsigned g_qkv [(size_t)M_TOT * 192];  // packed bf16x2: Q|K|V words
__device__ unsigned g_attn[(size_t)M_TOT * 64];   // packed bf16x2 (128 cols)
__device__ float g_xln [(size_t)M_TOT * 128];
__device__ float g_xres[(size_t)M_TOT * 128];
__device__ float g_ps  [256 * 4 * 4096];          // rpb+mask, C-frag order
__device__ unsigned g_wtf[98304];  // qkv bf16(rm) | proj bf16(frag) | fc1 bf16 | fc2 bf16

__device__ __forceinline__ int perm_row(int r) {
    int b_ = r >> 7, tt = r & 127;
    int b = b_ >> 8, w = b_ & 255;
    int wh = w >> 4, ww = w & 15;
    int t = tt >> 6, n = tt & 63;
    int i = n >> 3, j = n & 7;
    int oh = (wh * 8 + i + 4) & 127;
    int ow = (ww * 8 + j + 4) & 127;
    return (b * 2 + t) * 16384 + oh * 128 + ow;
}

__device__ __forceinline__ unsigned f2tf(float f) {
    unsigned u;
    asm("cvt.rna.tf32.f32 %0, %1;" : "=r"(u) : "f"(f));
    return u;
}
__device__ __forceinline__ float round_tf(float f) { return __uint_as_float(f2tf(f)); }

__device__ __forceinline__ unsigned pack_bf(float lo, float hi) {
    unsigned d;
    asm("cvt.rn.bf16x2.f32 %0, %1, %2;" : "=r"(d) : "f"(hi), "f"(lo));
    return d;
}

#define MMA_BF16(d, a0, a1, a2, a3, b0, b1)                                            \
    asm volatile(                                                                      \
        "mma.sync.aligned.m16n8k16.row.col.f32.bf16.bf16.f32 "                         \
        "{%0,%1,%2,%3},{%4,%5,%6,%7},{%8,%9},{%0,%1,%2,%3};"                           \
        : "+f"(d[0]), "+f"(d[1]), "+f"(d[2]), "+f"(d[3])                               \
        : "r"(a0), "r"(a1), "r"(a2), "r"(a3), "r"(b0), "r"(b1))

// ---------------- setup: weight conversion + rpb/mask table ----------------
__global__ void setup_kernel(const float* __restrict__ qkv_w, const float* __restrict__ proj_w,
                             const float* __restrict__ fc1_w, const float* __restrict__ fc2_w,
                             const float* __restrict__ rpb,
                             unsigned* __restrict__ wtf, float* __restrict__ ps) {
    int bid = blockIdx.x;
    int tid = threadIdx.x;
    if (bid < 384) {
        int i = bid * 256 + tid;
        if (i < 24576) {
            int n = i >> 6, w = i & 63;
            wtf[i] = pack_bf(qkv_w[n * 128 + 2 * w], qkv_w[n * 128 + 2 * w + 1]);
        } else if (i < 32768) {
            int j = i - 24576;
            int half = j & 1, pos = j >> 1;
            int lane = pos & 31, kc = (pos >> 5) & 7, n8 = pos >> 8;
            int g = lane >> 2, t = lane & 3;
            int n = n8 * 8 + g;
            int kb = 16 * kc + (half ? 8 : 0) + 2 * t;
            wtf[i] = pack_bf(proj_w[n * 128 + kb], proj_w[n * 128 + kb + 1]);
        } else if (i < 65536) {
            int j = i - 32768;
            int n = j >> 6, w = j & 63;
            wtf[i] = pack_bf(fc1_w[n * 128 + 2 * w], fc1_w[n * 128 + 2 * w + 1]);
        } else {
            int j = i - 65536;
            int n = j >> 8, w = j & 255;
            wtf[i] = pack_bf(fc2_w[n * 512 + 2 * w], fc2_w[n * 512 + 2 * w + 1]);
        }
        return;
    }
    int pb = bid - 384;
    int wwin = pb >> 2, head = pb & 3;
    int wh = wwin >> 4, ww = wwin & 15;
    float* dst = ps + (size_t)(wwin * 4 + head) * 4096;
#pragma unroll
    for (int it = 0; it < 16; it++) {
        int e = tid + it * 256;
        int qn = e >> 6, kn = e & 63;
        int qi2 = qn >> 3, qj = qn & 7, ki = kn >> 3, kj = kn & 7;
        int rel = (qi2 - ki + 7) * 15 + (qj - kj + 7);
        float v = rpb[rel * HEADS + head];
        int gqh = wh * 8 + qi2, gqw = ww * 8 + qj;
        int gkh = wh * 8 + ki,  gkw = ww * 8 + kj;
        int rq = (gqh < 120 ? 0 : (gqh < 124 ? 1 : 2)) * 3 + (gqw < 120 ? 0 : (gqw < 124 ? 1 : 2));
        int rk = (gkh < 120 ? 0 : (gkh < 124 ? 1 : 2)) * 3 + (gkw < 120 ? 0 : (gkw < 124 ? 1 : 2));
        if (rq != rk) v -= 100.0f;
        int qtile = qn >> 4, ntile = kn >> 3;
        int ln = (qn & 7) * 4 + ((kn & 7) >> 1);
        int reg = ((qn >> 3) & 1) * 2 + (kn & 1);
        dst[((qtile * 8 + ntile) * 32 + ln) * 4 + reg] = v;
    }
}

// ---------------- qkv GEMM (bf16): A staged once, weights streamed ----------------
#define QKV_SMEM ((8448 + 8448) * 4)
__global__ __launch_bounds__(512) void qkv_kernel(
    const float* __restrict__ xv, const unsigned* __restrict__ Wq_,
    const float* __restrict__ bias, unsigned* __restrict__ out) {
    extern __shared__ unsigned sm[];
    unsigned* XA = sm;
    unsigned* WB = sm + 8448;

    const uint4* Wg = reinterpret_cast<const uint4*>(Wq_);
    const int tid = threadIdx.x;
    const int lane = tid & 31;
    const int wid = tid >> 5;
    const int wm = wid >> 2, wn = wid & 3;
    const int g = lane >> 2, t = lane & 3;
    const int bm = blockIdx.x * 128;
    const float scale = 0.17677669529663687f;

#pragma unroll
    for (int it = 0; it < 8; it++) {
        int c = tid + it * 512;
        int row = c >> 5, kq = c & 31;
        int src = perm_row(bm + row);
        float4 v = *reinterpret_cast<const float4*>(xv + (size_t)src * 128 + kq * 4);
        int rg = ((row >> 4) * 2 + ((row >> 3) & 1)) * 528 + (row & 7) * 8;
        int w0 = 2 * kq, w1 = 2 * kq + 1;
        XA[rg + (w0 >> 3) * 66 + ((w0 >> 2) & 1) + 2 * (w0 & 3)] = pack_bf(v.x, v.y);
        XA[rg + (w1 >> 3) * 66 + ((w1 >> 2) & 1) + 2 * (w1 & 3)] = pack_bf(v.z, v.w);
    }

    int wsrc[2], wst[2];
#pragma unroll
    for (int it = 0; it < 2; it++) {
        int e = tid + it * 512;
        int n = e >> 4, wq = e & 15;
        wsrc[it] = n * 16 + wq;
        wst[it] = (n >> 3) * 528 + (wq >> 1) * 66 + (n & 7) * 8 + (wq & 1);
    }
    {
        uint4 v[2];
#pragma unroll
        for (int it = 0; it < 2; it++) v[it] = Wg[wsrc[it]];
#pragma unroll
        for (int it = 0; it < 2; it++) {
            WB[wst[it] + 0] = v[it].x; WB[wst[it] + 2] = v[it].y;
            WB[wst[it] + 4] = v[it].z; WB[wst[it] + 6] = v[it].w;
        }
    }
    __syncthreads();

    int p = 0;
    for (int c = 0; c < 6; c++) {
        uint4 wv[2];
        if (c < 5) {
#pragma unroll
            for (int it = 0; it < 2; it++) wv[it] = Wg[wsrc[it] + (c + 1) * 1024];
        }
        unsigned* Wp = WB + p * 4224;

        float accs[2][2][4];
#pragma unroll
        for (int mi = 0; mi < 2; mi++)
#pragma unroll
            for (int ni = 0; ni < 2; ni++)
#pragma unroll
                for (int q = 0; q < 4; q++) accs[mi][ni][q] = 0.f;

#pragma unroll
        for (int k16 = 0; k16 < 8; k16++) {
            unsigned a[2][4], b[2][2];
#pragma unroll
            for (int mi = 0; mi < 2; mi++) {
                int base = ((wm * 2 + mi) * 2) * 528 + k16 * 66 + lane * 2;
                uint2 q0 = *reinterpret_cast<const uint2*>(&XA[base]);
                uint2 q1 = *reinterpret_cast<const uint2*>(&XA[base + 528]);
                a[mi][0] = q0.x; a[mi][2] = q0.y;
                a[mi][1] = q1.x; a[mi][3] = q1.y;
            }
#pragma unroll
            for (int ni = 0; ni < 2; ni++) {
                uint2 q = *reinterpret_cast<const uint2*>(&Wp[(wn * 2 + ni) * 528 + k16 * 66 + lane * 2]);
                b[ni][0] = q.x; b[ni][1] = q.y;
            }
#pragma unroll
            for (int mi = 0; mi < 2; mi++)
#pragma unroll
                for (int ni = 0; ni < 2; ni++)
                    MMA_BF16(accs[mi][ni], a[mi][0], a[mi][1], a[mi][2], a[mi][3],
                             b[ni][0], b[ni][1]);
        }

        float sc = (c < 2) ? scale : 1.0f;
#pragma unroll
        for (int mi = 0; mi < 2; mi++) {
#pragma unroll
            for (int rh = 0; rh < 2; rh++) {
                int r = bm + wm * 32 + mi * 16 + g + rh * 8;
#pragma unroll
                for (int ni = 0; ni < 2; ni++) {
                    int cw = c * 32 + wn * 8 + ni * 4 + t;
                    int col = 2 * cw;
                    out[(size_t)r * 192 + cw] =
                        pack_bf((accs[mi][ni][rh * 2 + 0] + bias[col]) * sc,
                                (accs[mi][ni][rh * 2 + 1] + bias[col + 1]) * sc);
                }
            }
        }

        if (c < 5) {
            unsigned* Wn = WB + (p ^ 1) * 4224;
#pragma unroll
            for (int it = 0; it < 2; it++) {
                Wn[wst[it] + 0] = wv[it].x; Wn[wst[it] + 2] = wv[it].y;
                Wn[wst[it] + 4] = wv[it].z; Wn[wst[it] + 6] = wv[it].w;
            }
            p ^= 1;
        }
        __syncthreads();
    }
}

// ---------------- window attention: all bf16 (round-13 split version) ----------------
#define SM_QA 0
#define SM_KB 2112
#define SM_VB 4224
#define SMEM_ATTN (6336 * 4)

__global__ __launch_bounds__(256) void attn_kernel(const unsigned* __restrict__ qkv,
                                                   const float* __restrict__ ps,
                                                   unsigned* __restrict__ attout) {
    extern __shared__ unsigned sm[];
    unsigned* QA = sm + SM_QA;
    unsigned* KB = sm + SM_KB;
    unsigned* VB = sm + SM_VB;

    const int win = blockIdx.x, head = blockIdx.y;
    const int tid = threadIdx.x;
    const int lane = tid & 31, w = tid >> 5;
    const int g = lane >> 2, t = lane & 3;
    const float* psh = ps + (size_t)((win & 255) * 4 + head) * 4096;
    const uint4* qkv4 = reinterpret_cast<const uint4*>(qkv);

#pragma unroll
    for (int it = 0; it < 2; it++) {
        int e = tid + it * 256;
        int row = e >> 2, q4 = e & 3;
        size_t idx = ((size_t)(win * 128 + row)) * 48 + head * 4 + q4;
        uint4 qv = qkv4[idx];
        uint4 kv = qkv4[idx + 16];
        int rgq = ((row >> 4) * 2 + ((row >> 3) & 1)) * 132 + (row & 7) * 8;
        int rgk = (row >> 3) * 132 + (row & 7) * 8;
        unsigned qw[4] = {qv.x, qv.y, qv.z, qv.w};
        unsigned kw[4] = {kv.x, kv.y, kv.z, kv.w};
#pragma unroll
        for (int j = 0; j < 4; j++) {
            int wd = q4 * 4 + j;
            int off = (wd >> 3) * 66 + ((wd >> 2) & 1) + 2 * (wd & 3);
            QA[rgq + off] = qw[j];
            KB[rgk + off] = kw[j];
        }
    }
    {
        int e = tid;
        int tp = e >> 2, q4 = e & 3;
        size_t idxe = ((size_t)(win * 128 + 2 * tp)) * 48 + head * 4 + 32 + q4;
        uint4 ve = qkv4[idxe];
        uint4 vo = qkv4[idxe + 48];
        int kc = tp >> 3, kw2 = tp & 7;
        int off = (kw2 & 3) * 2 + (kw2 >> 2);
        unsigned ew[4] = {ve.x, ve.y, ve.z, ve.w};
        unsigned ow[4] = {vo.x, vo.y, vo.z, vo.w};
#pragma unroll
        for (int j = 0; j < 4; j++) {
            int wd = q4 * 4 + j;
            unsigned d0 = __byte_perm(ew[j], ow[j], 0x5410);
            unsigned d1 = __byte_perm(ew[j], ow[j], 0x7632);
            int n0 = 2 * wd, n1 = 2 * wd + 1;
            VB[(n0 >> 3) * 528 + kc * 66 + (n0 & 7) * 8 + off] = d0;
            VB[(n1 >> 3) * 528 + kc * 66 + (n1 & 7) * 8 + off] = d1;
        }
    }
    __syncthreads();

    float acc[16][4];
#pragma unroll
    for (int nt = 0; nt < 16; nt++)
#pragma unroll
        for (int i = 0; i < 4; i++) acc[nt][i] = 0.f;

#pragma unroll
    for (int k16 = 0; k16 < 2; k16++) {
        int abase = (w * 2) * 132 + k16 * 66 + lane * 2;
        uint2 q0 = *reinterpret_cast<const uint2*>(&QA[abase]);
        uint2 q1 = *reinterpret_cast<const uint2*>(&QA[abase + 132]);
#pragma unroll
        for (int nt = 0; nt < 16; nt++) {
            uint2 b = *reinterpret_cast<const uint2*>(&KB[nt * 132 + k16 * 66 + lane * 2]);
            MMA_BF16(acc[nt], q0.x, q1.x, q0.y, q1.y, b.x, b.y);
        }
    }

    const int qtile = w & 3;
    float m0 = -1e30f, m1 = -1e30f;
#pragma unroll
    for (int nt = 0; nt < 16; nt++) {
        float4 p = *reinterpret_cast<const float4*>(psh + ((qtile * 8 + (nt & 7)) * 32 + lane) * 4);
        acc[nt][0] += p.x; acc[nt][1] += p.y;
        acc[nt][2] += p.z; acc[nt][3] += p.w;
        m0 = fmaxf(m0, fmaxf(acc[nt][0], acc[nt][1]));
        m1 = fmaxf(m1, fmaxf(acc[nt][2], acc[nt][3]));
    }
    m0 = fmaxf(m0, __shfl_xor_sync(0xffffffffu, m0, 1));
    m0 = fmaxf(m0, __shfl_xor_sync(0xffffffffu, m0, 2));
    m1 = fmaxf(m1, __shfl_xor_sync(0xffffffffu, m1, 1));
    m1 = fmaxf(m1, __shfl_xor_sync(0xffffffffu, m1, 2));

    float l0 = 0.f, l1 = 0.f;
#pragma unroll
    for (int nt = 0; nt < 16; nt++) {
        acc[nt][0] = __expf(acc[nt][0] - m0);
        acc[nt][1] = __expf(acc[nt][1] - m0);
        acc[nt][2] = __expf(acc[nt][2] - m1);
        acc[nt][3] = __expf(acc[nt][3] - m1);
        l0 += acc[nt][0] + acc[nt][1];
        l1 += acc[nt][2] + acc[nt][3];
    }
    l0 += __shfl_xor_sync(0xffffffffu, l0, 1);
    l0 += __shfl_xor_sync(0xffffffffu, l0, 2);
    l1 += __shfl_xor_sync(0xffffffffu, l1, 1);
    l1 += __shfl_xor_sync(0xffffffffu, l1, 2);
    float inv0 = 1.0f / l0, inv1 = 1.0f / l1;

    float oacc[4][4];
#pragma unroll
    for (int n8 = 0; n8 < 4; n8++)
#pragma unroll
        for (int i = 0; i < 4; i++) oacc[n8][i] = 0.f;

#pragma unroll
    for (int kc = 0; kc < 8; kc++) {
        unsigned a0 = pack_bf(acc[2 * kc][0], acc[2 * kc][1]);
        unsigned a1 = pack_bf(acc[2 * kc][2], acc[2 * kc][3]);
        unsigned a2 = pack_bf(acc[2 * kc + 1][0], acc[2 * kc + 1][1]);
        unsigned a3 = pack_bf(acc[2 * kc + 1][2], acc[2 * kc + 1][3]);
#pragma unroll
        for (int n8 = 0; n8 < 4; n8++) {
            uint2 b = *reinterpret_cast<const uint2*>(&VB[n8 * 528 + kc * 66 + lane * 2]);
            MMA_BF16(oacc[n8], a0, a1, a2, a3, b.x, b.y);
        }
    }

    int r0 = win * 128 + w * 16 + g;
#pragma unroll
    for (int n8 = 0; n8 < 4; n8++) {
        int colw = head * 16 + n8 * 4 + t;
        attout[(size_t)r0 * 64 + colw]       = pack_bf(oacc[n8][0] * inv0, oacc[n8][1] * inv0);
        attout[(size_t)(r0 + 8) * 64 + colw] = pack_bf(oacc[n8][2] * inv1, oacc[n8][3] * inv1);
    }
}

// ---------------- proj (bf16) + scatter + residual + LN2 (round-13 version) ----------------
#define PROJ_SMEM (8448 * 4)
__global__ __launch_bounds__(256) void projln_kernel(
    const unsigned* __restrict__ attn, const unsigned* __restrict__ Wp_,
    const float* __restrict__ bias, const float* __restrict__ res,
    float* __restrict__ xres, float* __restrict__ xln,
    const float* __restrict__ gw, const float* __restrict__ bw) {
    extern __shared__ unsigned sm[];
    unsigned* OA = sm;
    __shared__ float smS[128][2], smQ[128][2];

    const int win = blockIdx.x;
    const int tid = threadIdx.x;
    const int lane = tid & 31, w = tid >> 5;
    const int g = lane >> 2, t = lane & 3;
    const int wm = w >> 1, wn = w & 1;

    const uint4* attn4 = reinterpret_cast<const uint4*>(attn);
#pragma unroll
    for (int it = 0; it < 8; it++) {
        int e = tid + it * 256;
        int row = e >> 4, q4 = e & 15;
        uint4 v = attn4[((size_t)(win * 128 + row)) * 16 + q4];
        int base = ((row >> 4) * 2 + ((row >> 3) & 1)) * 528 + (row & 7) * 8 +
                   (q4 >> 1) * 66 + (q4 & 1);
        OA[base + 0] = v.x; OA[base + 2] = v.y; OA[base + 4] = v.z; OA[base + 6] = v.w;
    }
    __syncthreads();

    const uint2* Wp2 = reinterpret_cast<const uint2*>(Wp_);
    float acc2[2][8][4];
#pragma unroll
    for (int mi = 0; mi < 2; mi++)
#pragma unroll
        for (int ni = 0; ni < 8; ni++)
#pragma unroll
            for (int q = 0; q < 4; q++) acc2[mi][ni][q] = 0.f;

#pragma unroll
    for (int k16 = 0; k16 < 8; k16++) {
        unsigned a[2][4];
#pragma unroll
        for (int mi = 0; mi < 2; mi++) {
            int base = ((wm * 2 + mi) * 2) * 528 + k16 * 66 + lane * 2;
            uint2 q0 = *reinterpret_cast<const uint2*>(&OA[base]);
            uint2 q1 = *reinterpret_cast<const uint2*>(&OA[base + 528]);
            a[mi][0] = q0.x; a[mi][2] = q0.y;
            a[mi][1] = q1.x; a[mi][3] = q1.y;
        }
#pragma unroll
        for (int ni = 0; ni < 8; ni++) {
            uint2 b = Wp2[((wn * 8 + ni) * 8 + k16) * 32 + lane];
#pragma unroll
            for (int mi = 0; mi < 2; mi++)
                MMA_BF16(acc2[mi][ni], a[mi][0], a[mi][1], a[mi][2], a[mi][3], b.x, b.y);
        }
    }

#pragma unroll
    for (int mi = 0; mi < 2; mi++) {
#pragma unroll
        for (int rh = 0; rh < 2; rh++) {
            int lrow = wm * 32 + mi * 16 + g + rh * 8;
            int xrow = perm_row(win * 128 + lrow);
            float v[16];
            float s = 0.f, q = 0.f;
#pragma unroll
            for (int ni = 0; ni < 8; ni++) {
                int cc = wn * 64 + ni * 8 + t * 2;
                float2 rr = *reinterpret_cast<const float2*>(res + (size_t)xrow * 128 + cc);
                float x0 = acc2[mi][ni][rh * 2 + 0] + bias[cc] + rr.x;
                float x1 = acc2[mi][ni][rh * 2 + 1] + bias[cc + 1] + rr.y;
                *reinterpret_cast<float2*>(xres + (size_t)xrow * 128 + cc) = make_float2(x0, x1);
                v[ni * 2 + 0] = x0; v[ni * 2 + 1] = x1;
                s += x0 + x1; q += x0 * x0 + x1 * x1;
            }
            s += __shfl_xor_sync(0xffffffffu, s, 1);
            s += __shfl_xor_sync(0xffffffffu, s, 2);
            q += __shfl_xor_sync(0xffffffffu, q, 1);
            q += __shfl_xor_sync(0xffffffffu, q, 2);
            if (t == 0) { smS[lrow][wn] = s; smQ[lrow][wn] = q; }
            __syncthreads();
            float S = smS[lrow][0] + smS[lrow][1];
            float Q = smQ[lrow][0] + smQ[lrow][1];
            float mu = S * (1.f / 128.f);
            float var = Q * (1.f / 128.f) - mu * mu;
            float rs = rsqrtf(var + 1e-5f);
#pragma unroll
            for (int ni = 0; ni < 8; ni++) {
                int cc = wn * 64 + ni * 8 + t * 2;
                float2 o;
                o.x = round_tf((v[ni * 2 + 0] - mu) * rs * gw[cc] + bw[cc]);
                o.y = round_tf((v[ni * 2 + 1] - mu) * rs * gw[cc + 1] + bw[cc + 1]);
                *reinterpret_cast<float2*>(xln + (size_t)xrow * 128 + cc) = o;
            }
        }
    }
}

// ---------------- fused MLP (bf16, reg-direct GEMM1->GEMM2 handoff) ----------------
// 256 threads, 8 warps; warp w owns rows [16w, 16w+16). No HH smem.
// smem words: XA 0..8448 | W1 8448..16896 (2x4224) | W2 16896..21120
#define MLP_SMEM (21120 * 4)
__global__ void __launch_bounds__(256, 2) mlp_kernel(
    const float* __restrict__ xln, const unsigned* __restrict__ W1g4_,
    const unsigned* __restrict__ W2g4_,
    const float* __restrict__ b1, const float* __restrict__ b2,
    const float* __restrict__ res, float* __restrict__ out,
    const float* __restrict__ gw, const float* __restrict__ bw) {
    extern __shared__ unsigned sm[];
    unsigned* XA = sm;
    unsigned* W1 = sm + 8448;
    unsigned* W2 = sm + 16896;

    const uint4* W1g = reinterpret_cast<const uint4*>(W1g4_);
    const uint4* W2g = reinterpret_cast<const uint4*>(W2g4_);

    const int tid = threadIdx.x;
    const int lane = tid & 31;
    const int w = tid >> 5;
    const int g = lane >> 2, t = lane & 3;
    const int bm = blockIdx.x * 128;

    // stage XA
#pragma unroll
    for (int it = 0; it < 16; it++) {
        int c = tid + it * 256;
        int row = c >> 5, kq = c & 31;
        float4 v = *reinterpret_cast<const float4*>(xln + (size_t)(bm + row) * 128 + kq * 4);
        int rg = ((row >> 4) * 2 + ((row >> 3) & 1)) * 528 + (row & 7) * 8;
        int w0 = 2 * kq, w1 = 2 * kq + 1;
        XA[rg + (w0 >> 3) * 66 + ((w0 >> 2) & 1) + 2 * (w0 & 3)] = pack_bf(v.x, v.y);
        XA[rg + (w1 >> 3) * 66 + ((w1 >> 2) & 1) + 2 * (w1 & 3)] = pack_bf(v.z, v.w);
    }

    // staging coords: W1 chunk 64n x 16 uint4 (1024), W2 chunk 128n x 8 uint4 (1024)
    int w1src[4], w1st[4], w2src[4], w2st[4];
#pragma unroll
    for (int it = 0; it < 4; it++) {
        int e = tid + it * 256;
        int n = e >> 4, wq = e & 15;
        w1src[it] = n * 16 + wq;             // + chunk*1024
        w1st[it] = (n >> 3) * 528 + (wq >> 1) * 66 + (n & 7) * 8 + (wq & 1);
        int n2 = e >> 3, wq2 = e & 7;
        w2src[it] = n2 * 64 + wq2;           // + chunk*8
        w2st[it] = (n2 >> 3) * 264 + (wq2 >> 1) * 66 + (n2 & 7) * 8 + (wq2 & 1);
    }

    // preload W1 chunk 0 into buffer 0
    {
        uint4 v[4];
#pragma unroll
        for (int it = 0; it < 4; it++) v[it] = W1g[w1src[it]];
#pragma unroll
        for (int it = 0; it < 4; it++) {
            W1[w1st[it] + 0] = v[it].x; W1[w1st[it] + 2] = v[it].y;
            W1[w1st[it] + 4] = v[it].z; W1[w1st[it] + 6] = v[it].w;
        }
    }
    __syncthreads();

    float acco[16][4];
#pragma unroll
    for (int ni = 0; ni < 16; ni++)
#pragma unroll
        for (int q = 0; q < 4; q++) acco[ni][q] = 0.f;

    int p = 0;
    for (int c = 0; c < 8; c++) {
        // prefetch W2 chunk c
        uint4 w2v[4];
#pragma unroll
        for (int it = 0; it < 4; it++) w2v[it] = W2g[w2src[it] + c * 8];

        // ---- GEMM1: S(m16 x n64) = X @ W1^T, K=128 ----
        float accs[8][4];
#pragma unroll
        for (int ni = 0; ni < 8; ni++)
#pragma unroll
            for (int q = 0; q < 4; q++) accs[ni][q] = 0.f;

        unsigned* W1p = W1 + p * 4224;
#pragma unroll
        for (int k16 = 0; k16 < 8; k16++) {
            int abase = (w * 2) * 528 + k16 * 66 + lane * 2;
            uint2 q0 = *reinterpret_cast<const uint2*>(&XA[abase]);
            uint2 q1 = *reinterpret_cast<const uint2*>(&XA[abase + 528]);
#pragma unroll
            for (int ni = 0; ni < 8; ni++) {
                uint2 b = *reinterpret_cast<const uint2*>(&W1p[ni * 528 + k16 * 66 + lane * 2]);
                MMA_BF16(accs[ni], q0.x, q1.x, q0.y, q1.y, b.x, b.y);
            }
        }

        // store W2 stage (safe: all warps past previous GEMM2 via last sync)
#pragma unroll
        for (int it = 0; it < 4; it++) {
            W2[w2st[it] + 0] = w2v[it].x; W2[w2st[it] + 2] = w2v[it].y;
            W2[w2st[it] + 4] = w2v[it].z; W2[w2st[it] + 6] = w2v[it].w;
        }

        // bias + gelu + pack into GEMM2 A fragments (C-frag -> A-frag identity)
        unsigned aw[4][4];
#pragma unroll
        for (int ni = 0; ni < 8; ni++) {
            int kl = c * 64 + ni * 8 + t * 2;
            float bb0 = b1[kl], bb1 = b1[kl + 1];
            float x0 = accs[ni][0] + bb0;
            float x1 = accs[ni][1] + bb1;
            float x2 = accs[ni][2] + bb0;
            float x3 = accs[ni][3] + bb1;
            x0 = 0.5f * x0 * (1.0f + erff(x0 * 0.7071067811865475f));
            x1 = 0.5f * x1 * (1.0f + erff(x1 * 0.7071067811865475f));
            x2 = 0.5f * x2 * (1.0f + erff(x2 * 0.7071067811865475f));
            x3 = 0.5f * x3 * (1.0f + erff(x3 * 0.7071067811865475f));
            int kc = ni >> 1;
            if ((ni & 1) == 0) {
                aw[kc][0] = pack_bf(x0, x1);
                aw[kc][1] = pack_bf(x2, x3);
            } else {
                aw[kc][2] = pack_bf(x0, x1);
                aw[kc][3] = pack_bf(x2, x3);
            }
        }
        __syncthreads();   // W2 visible

        // prefetch W1 chunk c+1
        uint4 w1v[4];
        if (c < 7) {
#pragma unroll
            for (int it = 0; it < 4; it++) w1v[it] = W1g[w1src[it] + (c + 1) * 1024];
        }

        // ---- GEMM2: out(m16 x n128) += H @ W2^T, K=64 (A from regs) ----
#pragma unroll
        for (int kc = 0; kc < 4; kc++) {
#pragma unroll
            for (int ni = 0; ni < 16; ni++) {
                uint2 b = *reinterpret_cast<const uint2*>(&W2[ni * 264 + kc * 66 + lane * 2]);
                MMA_BF16(acco[ni], aw[kc][0], aw[kc][1], aw[kc][2], aw[kc][3], b.x, b.y);
            }
        }

        if (c < 7) {
            unsigned* Wn = W1 + (p ^ 1) * 4224;
#pragma unroll
            for (int it = 0; it < 4; it++) {
                Wn[w1st[it] + 0] = w1v[it].x; Wn[w1st[it] + 2] = w1v[it].y;
                Wn[w1st[it] + 4] = w1v[it].z; Wn[w1st[it] + 6] = w1v[it].w;
            }
            p ^= 1;
        }
        __syncthreads();
    }

    // ---- epilogue: bias2 + residual + LN1 (quad-local, no smem) ----
#pragma unroll
    for (int rh = 0; rh < 2; rh++) {
        int r = bm + w * 16 + g + rh * 8;
        float v[32];
        float s = 0.f, q = 0.f;
#pragma unroll
        for (int ni = 0; ni < 16; ni++) {
            int cc = ni * 8 + t * 2;
            float2 rr = *reinterpret_cast<const float2*>(res + (size_t)r * 128 + cc);
            float x0 = acco[ni][rh * 2 + 0] + b2[cc] + rr.x;
            float x1 = acco[ni][rh * 2 + 1] + b2[cc + 1] + rr.y;
            v[ni * 2 + 0] = x0; v[ni * 2 + 1] = x1;
            s += x0 + x1; q += x0 * x0 + x1 * x1;
        }
        s += __shfl_xor_sync(0xffffffffu, s, 1);
        s += __shfl_xor_sync(0xffffffffu, s, 2);
        q += __shfl_xor_sync(0xffffffffu, q, 1);
        q += __shfl_xor_sync(0xffffffffu, q, 2);
        float mu = s * (1.f / 128.f);
        float var = q * (1.f / 128.f) - mu * mu;
        float rs = rsqrtf(var + 1e-5f);
#pragma unroll
        for (int ni = 0; ni < 16; ni++) {
            int cc = ni * 8 + t * 2;
            float2 o;
            o.x = (v[ni * 2 + 0] - mu) * rs * gw[cc] + bw[cc];
            o.y = (v[ni * 2 + 1] - mu) * rs * gw[cc + 1] + bw[cc + 1];
            *reinterpret_cast<float2*>(out + (size_t)r * 128 + cc) = o;
        }
    }
}

// ---------------- launch ----------------
extern "C" void kernel_launch(void* const* d_in, const int* in_sizes, int n_in,
                              void* d_out, int out_size) {
    const float* x_v    = (const float*)d_in[0];
    const float* qkv_w  = (const float*)d_in[1];
    const float* qkv_b  = (const float*)d_in[2];
    const float* proj_w = (const float*)d_in[3];
    const float* proj_b = (const float*)d_in[4];
    const float* rpb    = (const float*)d_in[5];
    const float* n1w    = (const float*)d_in[6];
    const float* n1b    = (const float*)d_in[7];
    const float* n2w    = (const float*)d_in[8];
    const float* n2b    = (const float*)d_in[9];
    const float* fc1w   = (const float*)d_in[10];
    const float* fc1b   = (const float*)d_in[11];
    const float* fc2w   = (const float*)d_in[12];
    const float* fc2b   = (const float*)d_in[13];
    float* out = (float*)d_out;

    float *xln, *xres, *ps;
    unsigned *qkvb, *attn, *wtf;
    cudaGetSymbolAddress((void**)&qkvb, g_qkv);
    cudaGetSymbolAddress((void**)&attn, g_attn);
    cudaGetSymbolAddress((void**)&xln,  g_xln);
    cudaGetSymbolAddress((void**)&xres, g_xres);
    cudaGetSymbolAddress((void**)&ps,   g_ps);
    cudaGetSymbolAddress((void**)&wtf,  g_wtf);

    cudaFuncSetAttribute(qkv_kernel, cudaFuncAttributeMaxDynamicSharedMemorySize, QKV_SMEM);
    cudaFuncSetAttribute(attn_kernel, cudaFuncAttributeMaxDynamicSharedMemorySize, SMEM_ATTN);
    cudaFuncSetAttribute(projln_kernel, cudaFuncAttributeMaxDynamicSharedMemorySize, PROJ_SMEM);
    cudaFuncSetAttribute(mlp_kernel, cudaFuncAttributeMaxDynamicSharedMemorySize, MLP_SMEM);

    // 0. setup: weights (bf16 packed) + rpb/mask table
    setup_kernel<<<1408, 256>>>(qkv_w, proj_w, fc1w, fc2w, rpb, wtf, ps);
    // 1. qkv (bf16), packed bf16x2 output
    qkv_kernel<<<1024, 512, QKV_SMEM>>>(x_v, wtf, qkv_b, qkvb);
    // 2. window attention (all bf16)
    attn_kernel<<<dim3(1024, HEADS), 256, SMEM_ATTN>>>(qkvb, ps, attn);
    // 3. proj (bf16) + scatter + residual + LN2
    projln_kernel<<<1024, 256, PROJ_SMEM>>>(attn, wtf + 24576, proj_b,
                                            x_v, xres, xln, n2w, n2b);
    // 4. fused MLP (bf16, reg handoff) -> final output
    mlp_kernel<<<1024, 256, MLP_SMEM>>>(xln, wtf + 32768, wtf + 65536,
                                        fc1b, fc2b, xres, out, n1w, n1b);
}

// round 16
// speedup vs baseline: 1.1108x; 1.0307x over previous
#include <cuda_runtime.h>
#include <math.h>

// ---------------- problem constants ----------------
#define M_TOT 131072
#define HEADS 4

// ---------------- scratch ----------------
__device__ unsigned g_qkv [(size_t)M_TOT * 192];  // packed bf16x2: Q|K|V words
__device__ unsigned g_attn[(size_t)M_TOT * 64];   // packed bf16x2 (128 cols)
__device__ float g_xln [(size_t)M_TOT * 128];
__device__ float g_xres[(size_t)M_TOT * 128];
__device__ float g_ps  [256 * 4 * 4096];          // rpb+mask, C-frag order
__device__ unsigned g_wtf[98304];  // qkv bf16(rm) | proj bf16(frag) | fc1 bf16 | fc2 bf16

__device__ __forceinline__ int perm_row(int r) {
    int b_ = r >> 7, tt = r & 127;
    int b = b_ >> 8, w = b_ & 255;
    int wh = w >> 4, ww = w & 15;
    int t = tt >> 6, n = tt & 63;
    int i = n >> 3, j = n & 7;
    int oh = (wh * 8 + i + 4) & 127;
    int ow = (ww * 8 + j + 4) & 127;
    return (b * 2 + t) * 16384 + oh * 128 + ow;
}

__device__ __forceinline__ unsigned f2tf(float f) {
    unsigned u;
    asm("cvt.rna.tf32.f32 %0, %1;" : "=r"(u) : "f"(f));
    return u;
}
__device__ __forceinline__ float round_tf(float f) { return __uint_as_float(f2tf(f)); }

__device__ __forceinline__ unsigned pack_bf(float lo, float hi) {
    unsigned d;
    asm("cvt.rn.bf16x2.f32 %0, %1, %2;" : "=r"(d) : "f"(hi), "f"(lo));
    return d;
}

#define MMA_BF16(d, a0, a1, a2, a3, b0, b1)                                            \
    asm volatile(                                                                      \
        "mma.sync.aligned.m16n8k16.row.col.f32.bf16.bf16.f32 "                         \
        "{%0,%1,%2,%3},{%4,%5,%6,%7},{%8,%9},{%0,%1,%2,%3};"                           \
        : "+f"(d[0]), "+f"(d[1]), "+f"(d[2]), "+f"(d[3])                               \
        : "r"(a0), "r"(a1), "r"(a2), "r"(a3), "r"(b0), "r"(b1))

// ---------------- setup: weight conversion + rpb/mask table ----------------
__global__ void setup_kernel(const float* __restrict__ qkv_w, const float* __restrict__ proj_w,
                             const float* __restrict__ fc1_w, const float* __restrict__ fc2_w,
                             const float* __restrict__ rpb,
                             unsigned* __restrict__ wtf, float* __restrict__ ps) {
    int bid = blockIdx.x;
    int tid = threadIdx.x;
    if (bid < 384) {
        int i = bid * 256 + tid;
        if (i < 24576) {
            int n = i >> 6, w = i & 63;
            wtf[i] = pack_bf(qkv_w[n * 128 + 2 * w], qkv_w[n * 128 + 2 * w + 1]);
        } else if (i < 32768) {
            int j = i - 24576;
            int half = j & 1, pos = j >> 1;
            int lane = pos & 31, kc = (pos >> 5) & 7, n8 = pos >> 8;
            int g = lane >> 2, t = lane & 3;
            int n = n8 * 8 + g;
            int kb = 16 * kc + (half ? 8 : 0) + 2 * t;
            wtf[i] = pack_bf(proj_w[n * 128 + kb], proj_w[n * 128 + kb + 1]);
        } else if (i < 65536) {
            int j = i - 32768;
            int n = j >> 6, w = j & 63;
            wtf[i] = pack_bf(fc1_w[n * 128 + 2 * w], fc1_w[n * 128 + 2 * w + 1]);
        } else {
            int j = i - 65536;
            int n = j >> 8, w = j & 255;
            wtf[i] = pack_bf(fc2_w[n * 512 + 2 * w], fc2_w[n * 512 + 2 * w + 1]);
        }
        return;
    }
    int pb = bid - 384;
    int wwin = pb >> 2, head = pb & 3;
    int wh = wwin >> 4, ww = wwin & 15;
    float* dst = ps + (size_t)(wwin * 4 + head) * 4096;
#pragma unroll
    for (int it = 0; it < 16; it++) {
        int e = tid + it * 256;
        int qn = e >> 6, kn = e & 63;
        int qi2 = qn >> 3, qj = qn & 7, ki = kn >> 3, kj = kn & 7;
        int rel = (qi2 - ki + 7) * 15 + (qj - kj + 7);
        float v = rpb[rel * HEADS + head];
        int gqh = wh * 8 + qi2, gqw = ww * 8 + qj;
        int gkh = wh * 8 + ki,  gkw = ww * 8 + kj;
        int rq = (gqh < 120 ? 0 : (gqh < 124 ? 1 : 2)) * 3 + (gqw < 120 ? 0 : (gqw < 124 ? 1 : 2));
        int rk = (gkh < 120 ? 0 : (gkh < 124 ? 1 : 2)) * 3 + (gkw < 120 ? 0 : (gkw < 124 ? 1 : 2));
        if (rq != rk) v -= 100.0f;
        int qtile = qn >> 4, ntile = kn >> 3;
        int ln = (qn & 7) * 4 + ((kn & 7) >> 1);
        int reg = ((qn >> 3) & 1) * 2 + (kn & 1);
        dst[((qtile * 8 + ntile) * 32 + ln) * 4 + reg] = v;
    }
}

// ---------------- qkv GEMM (bf16): A staged once, weights streamed ----------------
#define QKV_SMEM ((8448 + 8448) * 4)
__global__ __launch_bounds__(512) void qkv_kernel(
    const float* __restrict__ xv, const unsigned* __restrict__ Wq_,
    const float* __restrict__ bias, unsigned* __restrict__ out) {
    extern __shared__ unsigned sm[];
    unsigned* XA = sm;
    unsigned* WB = sm + 8448;

    const uint4* Wg = reinterpret_cast<const uint4*>(Wq_);
    const int tid = threadIdx.x;
    const int lane = tid & 31;
    const int wid = tid >> 5;
    const int wm = wid >> 2, wn = wid & 3;
    const int g = lane >> 2, t = lane & 3;
    const int bm = blockIdx.x * 128;
    const float scale = 0.17677669529663687f;

#pragma unroll
    for (int it = 0; it < 8; it++) {
        int c = tid + it * 512;
        int row = c >> 5, kq = c & 31;
        int src = perm_row(bm + row);
        float4 v = *reinterpret_cast<const float4*>(xv + (size_t)src * 128 + kq * 4);
        int rg = ((row >> 4) * 2 + ((row >> 3) & 1)) * 528 + (row & 7) * 8;
        int w0 = 2 * kq, w1 = 2 * kq + 1;
        XA[rg + (w0 >> 3) * 66 + ((w0 >> 2) & 1) + 2 * (w0 & 3)] = pack_bf(v.x, v.y);
        XA[rg + (w1 >> 3) * 66 + ((w1 >> 2) & 1) + 2 * (w1 & 3)] = pack_bf(v.z, v.w);
    }

    int wsrc[2], wst[2];
#pragma unroll
    for (int it = 0; it < 2; it++) {
        int e = tid + it * 512;
        int n = e >> 4, wq = e & 15;
        wsrc[it] = n * 16 + wq;
        wst[it] = (n >> 3) * 528 + (wq >> 1) * 66 + (n & 7) * 8 + (wq & 1);
    }
    {
        uint4 v[2];
#pragma unroll
        for (int it = 0; it < 2; it++) v[it] = Wg[wsrc[it]];
#pragma unroll
        for (int it = 0; it < 2; it++) {
            WB[wst[it] + 0] = v[it].x; WB[wst[it] + 2] = v[it].y;
            WB[wst[it] + 4] = v[it].z; WB[wst[it] + 6] = v[it].w;
        }
    }
    __syncthreads();

    int p = 0;
    for (int c = 0; c < 6; c++) {
        uint4 wv[2];
        if (c < 5) {
#pragma unroll
            for (int it = 0; it < 2; it++) wv[it] = Wg[wsrc[it] + (c + 1) * 1024];
        }
        unsigned* Wp = WB + p * 4224;

        float accs[2][2][4];
#pragma unroll
        for (int mi = 0; mi < 2; mi++)
#pragma unroll
            for (int ni = 0; ni < 2; ni++)
#pragma unroll
                for (int q = 0; q < 4; q++) accs[mi][ni][q] = 0.f;

#pragma unroll
        for (int k16 = 0; k16 < 8; k16++) {
            unsigned a[2][4], b[2][2];
#pragma unroll
            for (int mi = 0; mi < 2; mi++) {
                int base = ((wm * 2 + mi) * 2) * 528 + k16 * 66 + lane * 2;
                uint2 q0 = *reinterpret_cast<const uint2*>(&XA[base]);
                uint2 q1 = *reinterpret_cast<const uint2*>(&XA[base + 528]);
                a[mi][0] = q0.x; a[mi][2] = q0.y;
                a[mi][1] = q1.x; a[mi][3] = q1.y;
            }
#pragma unroll
            for (int ni = 0; ni < 2; ni++) {
                uint2 q = *reinterpret_cast<const uint2*>(&Wp[(wn * 2 + ni) * 528 + k16 * 66 + lane * 2]);
                b[ni][0] = q.x; b[ni][1] = q.y;
            }
#pragma unroll
            for (int mi = 0; mi < 2; mi++)
#pragma unroll
                for (int ni = 0; ni < 2; ni++)
                    MMA_BF16(accs[mi][ni], a[mi][0], a[mi][1], a[mi][2], a[mi][3],
                             b[ni][0], b[ni][1]);
        }

        float sc = (c < 2) ? scale : 1.0f;
#pragma unroll
        for (int mi = 0; mi < 2; mi++) {
#pragma unroll
            for (int rh = 0; rh < 2; rh++) {
                int r = bm + wm * 32 + mi * 16 + g + rh * 8;
#pragma unroll
                for (int ni = 0; ni < 2; ni++) {
                    int cw = c * 32 + wn * 8 + ni * 4 + t;
                    int col = 2 * cw;
                    out[(size_t)r * 192 + cw] =
                        pack_bf((accs[mi][ni][rh * 2 + 0] + bias[col]) * sc,
                                (accs[mi][ni][rh * 2 + 1] + bias[col + 1]) * sc);
                }
            }
        }

        if (c < 5) {
            unsigned* Wn = WB + (p ^ 1) * 4224;
#pragma unroll
            for (int it = 0; it < 2; it++) {
                Wn[wst[it] + 0] = wv[it].x; Wn[wst[it] + 2] = wv[it].y;
                Wn[wst[it] + 4] = wv[it].z; Wn[wst[it] + 6] = wv[it].w;
            }
            p ^= 1;
        }
        __syncthreads();
    }
}

// ---------------- window attention: all bf16 ----------------
#define SM_QA 0
#define SM_KB 2112
#define SM_VB 4224
#define SMEM_ATTN (6336 * 4)

__global__ __launch_bounds__(256) void attn_kernel(const unsigned* __restrict__ qkv,
                                                   const float* __restrict__ ps,
                                                   unsigned* __restrict__ attout) {
    extern __shared__ unsigned sm[];
    unsigned* QA = sm + SM_QA;
    unsigned* KB = sm + SM_KB;
    unsigned* VB = sm + SM_VB;

    const int win = blockIdx.x, head = blockIdx.y;
    const int tid = threadIdx.x;
    const int lane = tid & 31, w = tid >> 5;
    const int g = lane >> 2, t = lane & 3;
    const float* psh = ps + (size_t)((win & 255) * 4 + head) * 4096;
    const uint4* qkv4 = reinterpret_cast<const uint4*>(qkv);

#pragma unroll
    for (int it = 0; it < 2; it++) {
        int e = tid + it * 256;
        int row = e >> 2, q4 = e & 3;
        size_t idx = ((size_t)(win * 128 + row)) * 48 + head * 4 + q4;
        uint4 qv = qkv4[idx];
        uint4 kv = qkv4[idx + 16];
        int rgq = ((row >> 4) * 2 + ((row >> 3) & 1)) * 132 + (row & 7) * 8;
        int rgk = (row >> 3) * 132 + (row & 7) * 8;
        unsigned qw[4] = {qv.x, qv.y, qv.z, qv.w};
        unsigned kw[4] = {kv.x, kv.y, kv.z, kv.w};
#pragma unroll
        for (int j = 0; j < 4; j++) {
            int wd = q4 * 4 + j;
            int off = (wd >> 3) * 66 + ((wd >> 2) & 1) + 2 * (wd & 3);
            QA[rgq + off] = qw[j];
            KB[rgk + off] = kw[j];
        }
    }
    {
        int e = tid;
        int tp = e >> 2, q4 = e & 3;
        size_t idxe = ((size_t)(win * 128 + 2 * tp)) * 48 + head * 4 + 32 + q4;
        uint4 ve = qkv4[idxe];
        uint4 vo = qkv4[idxe + 48];
        int kc = tp >> 3, kw2 = tp & 7;
        int off = (kw2 & 3) * 2 + (kw2 >> 2);
        unsigned ew[4] = {ve.x, ve.y, ve.z, ve.w};
        unsigned ow[4] = {vo.x, vo.y, vo.z, vo.w};
#pragma unroll
        for (int j = 0; j < 4; j++) {
            int wd = q4 * 4 + j;
            unsigned d0 = __byte_perm(ew[j], ow[j], 0x5410);
            unsigned d1 = __byte_perm(ew[j], ow[j], 0x7632);
            int n0 = 2 * wd, n1 = 2 * wd + 1;
            VB[(n0 >> 3) * 528 + kc * 66 + (n0 & 7) * 8 + off] = d0;
            VB[(n1 >> 3) * 528 + kc * 66 + (n1 & 7) * 8 + off] = d1;
        }
    }
    __syncthreads();

    float acc[16][4];
#pragma unroll
    for (int nt = 0; nt < 16; nt++)
#pragma unroll
        for (int i = 0; i < 4; i++) acc[nt][i] = 0.f;

#pragma unroll
    for (int k16 = 0; k16 < 2; k16++) {
        int abase = (w * 2) * 132 + k16 * 66 + lane * 2;
        uint2 q0 = *reinterpret_cast<const uint2*>(&QA[abase]);
        uint2 q1 = *reinterpret_cast<const uint2*>(&QA[abase + 132]);
#pragma unroll
        for (int nt = 0; nt < 16; nt++) {
            uint2 b = *reinterpret_cast<const uint2*>(&KB[nt * 132 + k16 * 66 + lane * 2]);
            MMA_BF16(acc[nt], q0.x, q1.x, q0.y, q1.y, b.x, b.y);
        }
    }

    const int qtile = w & 3;
    float m0 = -1e30f, m1 = -1e30f;
#pragma unroll
    for (int nt = 0; nt < 16; nt++) {
        float4 p = *reinterpret_cast<const float4*>(psh + ((qtile * 8 + (nt & 7)) * 32 + lane) * 4);
        acc[nt][0] += p.x; acc[nt][1] += p.y;
        acc[nt][2] += p.z; acc[nt][3] += p.w;
        m0 = fmaxf(m0, fmaxf(acc[nt][0], acc[nt][1]));
        m1 = fmaxf(m1, fmaxf(acc[nt][2], acc[nt][3]));
    }
    m0 = fmaxf(m0, __shfl_xor_sync(0xffffffffu, m0, 1));
    m0 = fmaxf(m0, __shfl_xor_sync(0xffffffffu, m0, 2));
    m1 = fmaxf(m1, __shfl_xor_sync(0xffffffffu, m1, 1));
    m1 = fmaxf(m1, __shfl_xor_sync(0xffffffffu, m1, 2));

    float l0 = 0.f, l1 = 0.f;
#pragma unroll
    for (int nt = 0; nt < 16; nt++) {
        acc[nt][0] = __expf(acc[nt][0] - m0);
        acc[nt][1] = __expf(acc[nt][1] - m0);
        acc[nt][2] = __expf(acc[nt][2] - m1);
        acc[nt][3] = __expf(acc[nt][3] - m1);
        l0 += acc[nt][0] + acc[nt][1];
        l1 += acc[nt][2] + acc[nt][3];
    }
    l0 += __shfl_xor_sync(0xffffffffu, l0, 1);
    l0 += __shfl_xor_sync(0xffffffffu, l0, 2);
    l1 += __shfl_xor_sync(0xffffffffu, l1, 1);
    l1 += __shfl_xor_sync(0xffffffffu, l1, 2);
    float inv0 = 1.0f / l0, inv1 = 1.0f / l1;

    float oacc[4][4];
#pragma unroll
    for (int n8 = 0; n8 < 4; n8++)
#pragma unroll
        for (int i = 0; i < 4; i++) oacc[n8][i] = 0.f;

#pragma unroll
    for (int kc = 0; kc < 8; kc++) {
        unsigned a0 = pack_bf(acc[2 * kc][0], acc[2 * kc][1]);
        unsigned a1 = pack_bf(acc[2 * kc][2], acc[2 * kc][3]);
        unsigned a2 = pack_bf(acc[2 * kc + 1][0], acc[2 * kc + 1][1]);
        unsigned a3 = pack_bf(acc[2 * kc + 1][2], acc[2 * kc + 1][3]);
#pragma unroll
        for (int n8 = 0; n8 < 4; n8++) {
            uint2 b = *reinterpret_cast<const uint2*>(&VB[n8 * 528 + kc * 66 + lane * 2]);
            MMA_BF16(oacc[n8], a0, a1, a2, a3, b.x, b.y);
        }
    }

    int r0 = win * 128 + w * 16 + g;
#pragma unroll
    for (int n8 = 0; n8 < 4; n8++) {
        int colw = head * 16 + n8 * 4 + t;
        attout[(size_t)r0 * 64 + colw]       = pack_bf(oacc[n8][0] * inv0, oacc[n8][1] * inv0);
        attout[(size_t)(r0 + 8) * 64 + colw] = pack_bf(oacc[n8][2] * inv1, oacc[n8][3] * inv1);
    }
}

// ---------------- proj (bf16) + scatter + residual + LN2, BM=64 retile ----------------
#define PROJ_SMEM (4224 * 4)
__global__ __launch_bounds__(256) void projln_kernel(
    const unsigned* __restrict__ attn, const unsigned* __restrict__ Wp_,
    const float* __restrict__ bias, const float* __restrict__ res,
    float* __restrict__ xres, float* __restrict__ xln,
    const float* __restrict__ gw, const float* __restrict__ bw) {
    extern __shared__ unsigned sm[];
    unsigned* OA = sm;   // 8 rowgrps x 528
    __shared__ float smS[64][2], smQ[64][2];

    const int bm = blockIdx.x * 64;
    const int tid = threadIdx.x;
    const int lane = tid & 31, w = tid >> 5;
    const int g = lane >> 2, t = lane & 3;
    const int wm = w >> 1, wn = w & 1;   // 4m x 2n; warp tile m16 x n64

    // stage A: 64 rows x 16 uint4
    const uint4* attn4 = reinterpret_cast<const uint4*>(attn);
#pragma unroll
    for (int it = 0; it < 4; it++) {
        int e = tid + it * 256;
        int row = e >> 4, q4 = e & 15;
        uint4 v = attn4[((size_t)(bm + row)) * 16 + q4];
        int base = ((row >> 4) * 2 + ((row >> 3) & 1)) * 528 + (row & 7) * 8 +
                   (q4 >> 1) * 66 + (q4 & 1);
        OA[base + 0] = v.x; OA[base + 2] = v.y; OA[base + 4] = v.z; OA[base + 6] = v.w;
    }
    __syncthreads();

    const uint2* Wp2 = reinterpret_cast<const uint2*>(Wp_);
    float acc2[8][4];
#pragma unroll
    for (int ni = 0; ni < 8; ni++)
#pragma unroll
        for (int q = 0; q < 4; q++) acc2[ni][q] = 0.f;

#pragma unroll
    for (int k16 = 0; k16 < 8; k16++) {
        int base = (wm * 2) * 528 + k16 * 66 + lane * 2;
        uint2 q0 = *reinterpret_cast<const uint2*>(&OA[base]);
        uint2 q1 = *reinterpret_cast<const uint2*>(&OA[base + 528]);
#pragma unroll
        for (int ni = 0; ni < 8; ni++) {
            uint2 b = Wp2[((wn * 8 + ni) * 8 + k16) * 32 + lane];
            MMA_BF16(acc2[ni], q0.x, q1.x, q0.y, q1.y, b.x, b.y);
        }
    }

#pragma unroll
    for (int rh = 0; rh < 2; rh++) {
        int lrow = wm * 16 + g + rh * 8;
        int xrow = perm_row(bm + lrow);
        float v[16];
        float s = 0.f, q = 0.f;
#pragma unroll
        for (int ni = 0; ni < 8; ni++) {
            int cc = wn * 64 + ni * 8 + t * 2;
            float2 rr = *reinterpret_cast<const float2*>(res + (size_t)xrow * 128 + cc);
            float x0 = acc2[ni][rh * 2 + 0] + bias[cc] + rr.x;
            float x1 = acc2[ni][rh * 2 + 1] + bias[cc + 1] + rr.y;
            *reinterpret_cast<float2*>(xres + (size_t)xrow * 128 + cc) = make_float2(x0, x1);
            v[ni * 2 + 0] = x0; v[ni * 2 + 1] = x1;
            s += x0 + x1; q += x0 * x0 + x1 * x1;
        }
        s += __shfl_xor_sync(0xffffffffu, s, 1);
        s += __shfl_xor_sync(0xffffffffu, s, 2);
        q += __shfl_xor_sync(0xffffffffu, q, 1);
        q += __shfl_xor_sync(0xffffffffu, q, 2);
        if (t == 0) { smS[lrow][wn] = s; smQ[lrow][wn] = q; }
        __syncthreads();
        float S = smS[lrow][0] + smS[lrow][1];
        float Q = smQ[lrow][0] + smQ[lrow][1];
        float mu = S * (1.f / 128.f);
        float var = Q * (1.f / 128.f) - mu * mu;
        float rs = rsqrtf(var + 1e-5f);
#pragma unroll
        for (int ni = 0; ni < 8; ni++) {
            int cc = wn * 64 + ni * 8 + t * 2;
            float2 o;
            o.x = round_tf((v[ni * 2 + 0] - mu) * rs * gw[cc] + bw[cc]);
            o.y = round_tf((v[ni * 2 + 1] - mu) * rs * gw[cc + 1] + bw[cc + 1]);
            *reinterpret_cast<float2*>(xln + (size_t)xrow * 128 + cc) = o;
        }
    }
}

// ---------------- fused MLP (bf16, reg-direct GEMM1->GEMM2 handoff) ----------------
#define MLP_SMEM (21120 * 4)
__global__ void __launch_bounds__(256, 2) mlp_kernel(
    const float* __restrict__ xln, const unsigned* __restrict__ W1g4_,
    const unsigned* __restrict__ W2g4_,
    const float* __restrict__ b1, const float* __restrict__ b2,
    const float* __restrict__ res, float* __restrict__ out,
    const float* __restrict__ gw, const float* __restrict__ bw) {
    extern __shared__ unsigned sm[];
    unsigned* XA = sm;
    unsigned* W1 = sm + 8448;
    unsigned* W2 = sm + 16896;

    const uint4* W1g = reinterpret_cast<const uint4*>(W1g4_);
    const uint4* W2g = reinterpret_cast<const uint4*>(W2g4_);

    const int tid = threadIdx.x;
    const int lane = tid & 31;
    const int w = tid >> 5;
    const int g = lane >> 2, t = lane & 3;
    const int bm = blockIdx.x * 128;

#pragma unroll
    for (int it = 0; it < 16; it++) {
        int c = tid + it * 256;
        int row = c >> 5, kq = c & 31;
        float4 v = *reinterpret_cast<const float4*>(xln + (size_t)(bm + row) * 128 + kq * 4);
        int rg = ((row >> 4) * 2 + ((row >> 3) & 1)) * 528 + (row & 7) * 8;
        int w0 = 2 * kq, w1 = 2 * kq + 1;
        XA[rg + (w0 >> 3) * 66 + ((w0 >> 2) & 1) + 2 * (w0 & 3)] = pack_bf(v.x, v.y);
        XA[rg + (w1 >> 3) * 66 + ((w1 >> 2) & 1) + 2 * (w1 & 3)] = pack_bf(v.z, v.w);
    }

    int w1src[4], w1st[4], w2src[4], w2st[4];
#pragma unroll
    for (int it = 0; it < 4; it++) {
        int e = tid + it * 256;
        int n = e >> 4, wq = e & 15;
        w1src[it] = n * 16 + wq;
        w1st[it] = (n >> 3) * 528 + (wq >> 1) * 66 + (n & 7) * 8 + (wq & 1);
        int n2 = e >> 3, wq2 = e & 7;
        w2src[it] = n2 * 64 + wq2;
        w2st[it] = (n2 >> 3) * 264 + (wq2 >> 1) * 66 + (n2 & 7) * 8 + (wq2 & 1);
    }

    {
        uint4 v[4];
#pragma unroll
        for (int it = 0; it < 4; it++) v[it] = W1g[w1src[it]];
#pragma unroll
        for (int it = 0; it < 4; it++) {
            W1[w1st[it] + 0] = v[it].x; W1[w1st[it] + 2] = v[it].y;
            W1[w1st[it] + 4] = v[it].z; W1[w1st[it] + 6] = v[it].w;
        }
    }
    __syncthreads();

    float acco[16][4];
#pragma unroll
    for (int ni = 0; ni < 16; ni++)
#pragma unroll
        for (int q = 0; q < 4; q++) acco[ni][q] = 0.f;

    int p = 0;
    for (int c = 0; c < 8; c++) {
        uint4 w2v[4];
#pragma unroll
        for (int it = 0; it < 4; it++) w2v[it] = W2g[w2src[it] + c * 8];

        float accs[8][4];
#pragma unroll
        for (int ni = 0; ni < 8; ni++)
#pragma unroll
            for (int q = 0; q < 4; q++) accs[ni][q] = 0.f;

        unsigned* W1p = W1 + p * 4224;
#pragma unroll
        for (int k16 = 0; k16 < 8; k16++) {
            int abase = (w * 2) * 528 + k16 * 66 + lane * 2;
            uint2 q0 = *reinterpret_cast<const uint2*>(&XA[abase]);
            uint2 q1 = *reinterpret_cast<const uint2*>(&XA[abase + 528]);
#pragma unroll
            for (int ni = 0; ni < 8; ni++) {
                uint2 b = *reinterpret_cast<const uint2*>(&W1p[ni * 528 + k16 * 66 + lane * 2]);
                MMA_BF16(accs[ni], q0.x, q1.x, q0.y, q1.y, b.x, b.y);
            }
        }

#pragma unroll
        for (int it = 0; it < 4; it++) {
            W2[w2st[it] + 0] = w2v[it].x; W2[w2st[it] + 2] = w2v[it].y;
            W2[w2st[it] + 4] = w2v[it].z; W2[w2st[it] + 6] = w2v[it].w;
        }

        unsigned aw[4][4];
#pragma unroll
        for (int ni = 0; ni < 8; ni++) {
            int kl = c * 64 + ni * 8 + t * 2;
            float bb0 = b1[kl], bb1 = b1[kl + 1];
            float x0 = accs[ni][0] + bb0;
            float x1 = accs[ni][1] + bb1;
            float x2 = accs[ni][2] + bb0;
            float x3 = accs[ni][3] + bb1;
            x0 = 0.5f * x0 * (1.0f + erff(x0 * 0.7071067811865475f));
            x1 = 0.5f * x1 * (1.0f + erff(x1 * 0.7071067811865475f));
            x2 = 0.5f * x2 * (1.0f + erff(x2 * 0.7071067811865475f));
            x3 = 0.5f * x3 * (1.0f + erff(x3 * 0.7071067811865475f));
            int kc = ni >> 1;
            if ((ni & 1) == 0) {
                aw[kc][0] = pack_bf(x0, x1);
                aw[kc][1] = pack_bf(x2, x3);
            } else {
                aw[kc][2] = pack_bf(x0, x1);
                aw[kc][3] = pack_bf(x2, x3);
            }
        }
        __syncthreads();

        uint4 w1v[4];
        if (c < 7) {
#pragma unroll
            for (int it = 0; it < 4; it++) w1v[it] = W1g[w1src[it] + (c + 1) * 1024];
        }

#pragma unroll
        for (int kc = 0; kc < 4; kc++) {
#pragma unroll
            for (int ni = 0; ni < 16; ni++) {
                uint2 b = *reinterpret_cast<const uint2*>(&W2[ni * 264 + kc * 66 + lane * 2]);
                MMA_BF16(acco[ni], aw[kc][0], aw[kc][1], aw[kc][2], aw[kc][3], b.x, b.y);
            }
        }

        if (c < 7) {
            unsigned* Wn = W1 + (p ^ 1) * 4224;
#pragma unroll
            for (int it = 0; it < 4; it++) {
                Wn[w1st[it] + 0] = w1v[it].x; Wn[w1st[it] + 2] = w1v[it].y;
                Wn[w1st[it] + 4] = w1v[it].z; Wn[w1st[it] + 6] = w1v[it].w;
            }
            p ^= 1;
        }
        __syncthreads();
    }

#pragma unroll
    for (int rh = 0; rh < 2; rh++) {
        int r = bm + w * 16 + g + rh * 8;
        float v[32];
        float s = 0.f, q = 0.f;
#pragma unroll
        for (int ni = 0; ni < 16; ni++) {
            int cc = ni * 8 + t * 2;
            float2 rr = *reinterpret_cast<const float2*>(res + (size_t)r * 128 + cc);
            float x0 = acco[ni][rh * 2 + 0] + b2[cc] + rr.x;
            float x1 = acco[ni][rh * 2 + 1] + b2[cc + 1] + rr.y;
            v[ni * 2 + 0] = x0; v[ni * 2 + 1] = x1;
            s += x0 + x1; q += x0 * x0 + x1 * x1;
        }
        s += __shfl_xor_sync(0xffffffffu, s, 1);
        s += __shfl_xor_sync(0xffffffffu, s, 2);
        q += __shfl_xor_sync(0xffffffffu, q, 1);
        q += __shfl_xor_sync(0xffffffffu, q, 2);
        float mu = s * (1.f / 128.f);
        float var = q * (1.f / 128.f) - mu * mu;
        float rs = rsqrtf(var + 1e-5f);
#pragma unroll
        for (int ni = 0; ni < 16; ni++) {
            int cc = ni * 8 + t * 2;
            float2 o;
            o.x = (v[ni * 2 + 0] - mu) * rs * gw[cc] + bw[cc];
            o.y = (v[ni * 2 + 1] - mu) * rs * gw[cc + 1] + bw[cc + 1];
            *reinterpret_cast<float2*>(out + (size_t)r * 128 + cc) = o;
        }
    }
}

// ---------------- launch ----------------
extern "C" void kernel_launch(void* const* d_in, const int* in_sizes, int n_in,
                              void* d_out, int out_size) {
    const float* x_v    = (const float*)d_in[0];
    const float* qkv_w  = (const float*)d_in[1];
    const float* qkv_b  = (const float*)d_in[2];
    const float* proj_w = (const float*)d_in[3];
    const float* proj_b = (const float*)d_in[4];
    const float* rpb    = (const float*)d_in[5];
    const float* n1w    = (const float*)d_in[6];
    const float* n1b    = (const float*)d_in[7];
    const float* n2w    = (const float*)d_in[8];
    const float* n2b    = (const float*)d_in[9];
    const float* fc1w   = (const float*)d_in[10];
    const float* fc1b   = (const float*)d_in[11];
    const float* fc2w   = (const float*)d_in[12];
    const float* fc2b   = (const float*)d_in[13];
    float* out = (float*)d_out;

    float *xln, *xres, *ps;
    unsigned *qkvb, *attn, *wtf;
    cudaGetSymbolAddress((void**)&qkvb, g_qkv);
    cudaGetSymbolAddress((void**)&attn, g_attn);
    cudaGetSymbolAddress((void**)&xln,  g_xln);
    cudaGetSymbolAddress((void**)&xres, g_xres);
    cudaGetSymbolAddress((void**)&ps,   g_ps);
    cudaGetSymbolAddress((void**)&wtf,  g_wtf);

    cudaFuncSetAttribute(qkv_kernel, cudaFuncAttributeMaxDynamicSharedMemorySize, QKV_SMEM);
    cudaFuncSetAttribute(attn_kernel, cudaFuncAttributeMaxDynamicSharedMemorySize, SMEM_ATTN);
    cudaFuncSetAttribute(projln_kernel, cudaFuncAttributeMaxDynamicSharedMemorySize, PROJ_SMEM);
    cudaFuncSetAttribute(mlp_kernel, cudaFuncAttributeMaxDynamicSharedMemorySize, MLP_SMEM);

    // 0. setup: weights (bf16 packed) + rpb/mask table
    setup_kernel<<<1408, 256>>>(qkv_w, proj_w, fc1w, fc2w, rpb, wtf, ps);
    // 1. qkv (bf16), packed bf16x2 output
    qkv_kernel<<<1024, 512, QKV_SMEM>>>(x_v, wtf, qkv_b, qkvb);
    // 2. window attention (all bf16)
    attn_kernel<<<dim3(1024, HEADS), 256, SMEM_ATTN>>>(qkvb, ps, attn);
    // 3. proj (bf16) + scatter + residual + LN2  (BM=64 retile)
    projln_kernel<<<2048, 256, PROJ_SMEM>>>(attn, wtf + 24576, proj_b,
                                            x_v, xres, xln, n2w, n2b);
    // 4. fused MLP (bf16, reg handoff) -> final output
    mlp_kernel<<<1024, 256, MLP_SMEM>>>(xln, wtf + 32768, wtf + 65536,
                                        fc1b, fc2b, xres, out, n1w, n1b);
}

// round 17
// speedup vs baseline: 1.1349x; 1.0217x over previous
#include <cuda_runtime.h>
#include <math.h>

// ---------------- problem constants ----------------
#define M_TOT 131072
#define HEADS 4

// ---------------- scratch ----------------
__device__ unsigned g_qkv [(size_t)M_TOT * 192];  // packed bf16x2: Q|K|V words
__device__ unsigned g_attn[(size_t)M_TOT * 64];   // packed bf16x2 (128 cols)
__device__ unsigned g_xln [(size_t)M_TOT * 64];   // packed bf16x2 LN2 output
__device__ float g_xres[(size_t)M_TOT * 128];
__device__ float g_ps  [256 * 4 * 4096];          // rpb+mask, C-frag order
__device__ unsigned g_wtf[98304];  // qkv bf16(rm) | proj bf16(frag) | fc1 bf16 | fc2 bf16

__device__ __forceinline__ int perm_row(int r) {
    int b_ = r >> 7, tt = r & 127;
    int b = b_ >> 8, w = b_ & 255;
    int wh = w >> 4, ww = w & 15;
    int t = tt >> 6, n = tt & 63;
    int i = n >> 3, j = n & 7;
    int oh = (wh * 8 + i + 4) & 127;
    int ow = (ww * 8 + j + 4) & 127;
    return (b * 2 + t) * 16384 + oh * 128 + ow;
}

__device__ __forceinline__ unsigned pack_bf(float lo, float hi) {
    unsigned d;
    asm("cvt.rn.bf16x2.f32 %0, %1, %2;" : "=r"(d) : "f"(hi), "f"(lo));
    return d;
}

#define MMA_BF16(d, a0, a1, a2, a3, b0, b1)                                            \
    asm volatile(                                                                      \
        "mma.sync.aligned.m16n8k16.row.col.f32.bf16.bf16.f32 "                         \
        "{%0,%1,%2,%3},{%4,%5,%6,%7},{%8,%9},{%0,%1,%2,%3};"                           \
        : "+f"(d[0]), "+f"(d[1]), "+f"(d[2]), "+f"(d[3])                               \
        : "r"(a0), "r"(a1), "r"(a2), "r"(a3), "r"(b0), "r"(b1))

// ---------------- setup: weight conversion + rpb/mask table ----------------
__global__ void setup_kernel(const float* __restrict__ qkv_w, const float* __restrict__ proj_w,
                             const float* __restrict__ fc1_w, const float* __restrict__ fc2_w,
                             const float* __restrict__ rpb,
                             unsigned* __restrict__ wtf, float* __restrict__ ps) {
    int bid = blockIdx.x;
    int tid = threadIdx.x;
    if (bid < 384) {
        int i = bid * 256 + tid;
        if (i < 24576) {
            int n = i >> 6, w = i & 63;
            wtf[i] = pack_bf(qkv_w[n * 128 + 2 * w], qkv_w[n * 128 + 2 * w + 1]);
        } else if (i < 32768) {
            int j = i - 24576;
            int half = j & 1, pos = j >> 1;
            int lane = pos & 31, kc = (pos >> 5) & 7, n8 = pos >> 8;
            int g = lane >> 2, t = lane & 3;
            int n = n8 * 8 + g;
            int kb = 16 * kc + (half ? 8 : 0) + 2 * t;
            wtf[i] = pack_bf(proj_w[n * 128 + kb], proj_w[n * 128 + kb + 1]);
        } else if (i < 65536) {
            int j = i - 32768;
            int n = j >> 6, w = j & 63;
            wtf[i] = pack_bf(fc1_w[n * 128 + 2 * w], fc1_w[n * 128 + 2 * w + 1]);
        } else {
            int j = i - 65536;
            int n = j >> 8, w = j & 255;
            wtf[i] = pack_bf(fc2_w[n * 512 + 2 * w], fc2_w[n * 512 + 2 * w + 1]);
        }
        return;
    }
    int pb = bid - 384;
    int wwin = pb >> 2, head = pb & 3;
    int wh = wwin >> 4, ww = wwin & 15;
    float* dst = ps + (size_t)(wwin * 4 + head) * 4096;
#pragma unroll
    for (int it = 0; it < 16; it++) {
        int e = tid + it * 256;
        int qn = e >> 6, kn = e & 63;
        int qi2 = qn >> 3, qj = qn & 7, ki = kn >> 3, kj = kn & 7;
        int rel = (qi2 - ki + 7) * 15 + (qj - kj + 7);
        float v = rpb[rel * HEADS + head];
        int gqh = wh * 8 + qi2, gqw = ww * 8 + qj;
        int gkh = wh * 8 + ki,  gkw = ww * 8 + kj;
        int rq = (gqh < 120 ? 0 : (gqh < 124 ? 1 : 2)) * 3 + (gqw < 120 ? 0 : (gqw < 124 ? 1 : 2));
        int rk = (gkh < 120 ? 0 : (gkh < 124 ? 1 : 2)) * 3 + (gkw < 120 ? 0 : (gkw < 124 ? 1 : 2));
        if (rq != rk) v -= 100.0f;
        int qtile = qn >> 4, ntile = kn >> 3;
        int ln = (qn & 7) * 4 + ((kn & 7) >> 1);
        int reg = ((qn >> 3) & 1) * 2 + (kn & 1);
        dst[((qtile * 8 + ntile) * 32 + ln) * 4 + reg] = v;
    }
}

// ---------------- qkv GEMM (bf16): A staged once, weights streamed ----------------
#define QKV_SMEM ((8448 + 8448) * 4)
__global__ __launch_bounds__(512) void qkv_kernel(
    const float* __restrict__ xv, const unsigned* __restrict__ Wq_,
    const float* __restrict__ bias, unsigned* __restrict__ out) {
    extern __shared__ unsigned sm[];
    unsigned* XA = sm;
    unsigned* WB = sm + 8448;

    const uint4* Wg = reinterpret_cast<const uint4*>(Wq_);
    const int tid = threadIdx.x;
    const int lane = tid & 31;
    const int wid = tid >> 5;
    const int wm = wid >> 2, wn = wid & 3;
    const int g = lane >> 2, t = lane & 3;
    const int bm = blockIdx.x * 128;
    const float scale = 0.17677669529663687f;

#pragma unroll
    for (int it = 0; it < 8; it++) {
        int c = tid + it * 512;
        int row = c >> 5, kq = c & 31;
        int src = perm_row(bm + row);
        float4 v = *reinterpret_cast<const float4*>(xv + (size_t)src * 128 + kq * 4);
        int rg = ((row >> 4) * 2 + ((row >> 3) & 1)) * 528 + (row & 7) * 8;
        int w0 = 2 * kq, w1 = 2 * kq + 1;
        XA[rg + (w0 >> 3) * 66 + ((w0 >> 2) & 1) + 2 * (w0 & 3)] = pack_bf(v.x, v.y);
        XA[rg + (w1 >> 3) * 66 + ((w1 >> 2) & 1) + 2 * (w1 & 3)] = pack_bf(v.z, v.w);
    }

    int wsrc[2], wst[2];
#pragma unroll
    for (int it = 0; it < 2; it++) {
        int e = tid + it * 512;
        int n = e >> 4, wq = e & 15;
        wsrc[it] = n * 16 + wq;
        wst[it] = (n >> 3) * 528 + (wq >> 1) * 66 + (n & 7) * 8 + (wq & 1);
    }
    {
        uint4 v[2];
#pragma unroll
        for (int it = 0; it < 2; it++) v[it] = Wg[wsrc[it]];
#pragma unroll
        for (int it = 0; it < 2; it++) {
            WB[wst[it] + 0] = v[it].x; WB[wst[it] + 2] = v[it].y;
            WB[wst[it] + 4] = v[it].z; WB[wst[it] + 6] = v[it].w;
        }
    }
    __syncthreads();

    int p = 0;
    for (int c = 0; c < 6; c++) {
        uint4 wv[2];
        if (c < 5) {
#pragma unroll
            for (int it = 0; it < 2; it++) wv[it] = Wg[wsrc[it] + (c + 1) * 1024];
        }
        unsigned* Wp = WB + p * 4224;

        float accs[2][2][4];
#pragma unroll
        for (int mi = 0; mi < 2; mi++)
#pragma unroll
            for (int ni = 0; ni < 2; ni++)
#pragma unroll
                for (int q = 0; q < 4; q++) accs[mi][ni][q] = 0.f;

#pragma unroll
        for (int k16 = 0; k16 < 8; k16++) {
            unsigned a[2][4], b[2][2];
#pragma unroll
            for (int mi = 0; mi < 2; mi++) {
                int base = ((wm * 2 + mi) * 2) * 528 + k16 * 66 + lane * 2;
                uint2 q0 = *reinterpret_cast<const uint2*>(&XA[base]);
                uint2 q1 = *reinterpret_cast<const uint2*>(&XA[base + 528]);
                a[mi][0] = q0.x; a[mi][2] = q0.y;
                a[mi][1] = q1.x; a[mi][3] = q1.y;
            }
#pragma unroll
            for (int ni = 0; ni < 2; ni++) {
                uint2 q = *reinterpret_cast<const uint2*>(&Wp[(wn * 2 + ni) * 528 + k16 * 66 + lane * 2]);
                b[ni][0] = q.x; b[ni][1] = q.y;
            }
#pragma unroll
            for (int mi = 0; mi < 2; mi++)
#pragma unroll
                for (int ni = 0; ni < 2; ni++)
                    MMA_BF16(accs[mi][ni], a[mi][0], a[mi][1], a[mi][2], a[mi][3],
                             b[ni][0], b[ni][1]);
        }

        float sc = (c < 2) ? scale : 1.0f;
#pragma unroll
        for (int mi = 0; mi < 2; mi++) {
#pragma unroll
            for (int rh = 0; rh < 2; rh++) {
                int r = bm + wm * 32 + mi * 16 + g + rh * 8;
#pragma unroll
                for (int ni = 0; ni < 2; ni++) {
                    int cw = c * 32 + wn * 8 + ni * 4 + t;
                    int col = 2 * cw;
                    out[(size_t)r * 192 + cw] =
                        pack_bf((accs[mi][ni][rh * 2 + 0] + bias[col]) * sc,
                                (accs[mi][ni][rh * 2 + 1] + bias[col + 1]) * sc);
                }
            }
        }

        if (c < 5) {
            unsigned* Wn = WB + (p ^ 1) * 4224;
#pragma unroll
            for (int it = 0; it < 2; it++) {
                Wn[wst[it] + 0] = wv[it].x; Wn[wst[it] + 2] = wv[it].y;
                Wn[wst[it] + 4] = wv[it].z; Wn[wst[it] + 6] = wv[it].w;
            }
            p ^= 1;
        }
        __syncthreads();
    }
}

// ---------------- window attention: all bf16 ----------------
#define SM_QA 0
#define SM_KB 2112
#define SM_VB 4224
#define SMEM_ATTN (6336 * 4)

__global__ __launch_bounds__(256) void attn_kernel(const unsigned* __restrict__ qkv,
                                                   const float* __restrict__ ps,
                                                   unsigned* __restrict__ attout) {
    extern __shared__ unsigned sm[];
    unsigned* QA = sm + SM_QA;
    unsigned* KB = sm + SM_KB;
    unsigned* VB = sm + SM_VB;

    const int win = blockIdx.x, head = blockIdx.y;
    const int tid = threadIdx.x;
    const int lane = tid & 31, w = tid >> 5;
    const int g = lane >> 2, t = lane & 3;
    const float* psh = ps + (size_t)((win & 255) * 4 + head) * 4096;
    const uint4* qkv4 = reinterpret_cast<const uint4*>(qkv);

#pragma unroll
    for (int it = 0; it < 2; it++) {
        int e = tid + it * 256;
        int row = e >> 2, q4 = e & 3;
        size_t idx = ((size_t)(win * 128 + row)) * 48 + head * 4 + q4;
        uint4 qv = qkv4[idx];
        uint4 kv = qkv4[idx + 16];
        int rgq = ((row >> 4) * 2 + ((row >> 3) & 1)) * 132 + (row & 7) * 8;
        int rgk = (row >> 3) * 132 + (row & 7) * 8;
        unsigned qw[4] = {qv.x, qv.y, qv.z, qv.w};
        unsigned kw[4] = {kv.x, kv.y, kv.z, kv.w};
#pragma unroll
        for (int j = 0; j < 4; j++) {
            int wd = q4 * 4 + j;
            int off = (wd >> 3) * 66 + ((wd >> 2) & 1) + 2 * (wd & 3);
            QA[rgq + off] = qw[j];
            KB[rgk + off] = kw[j];
        }
    }
    {
        int e = tid;
        int tp = e >> 2, q4 = e & 3;
        size_t idxe = ((size_t)(win * 128 + 2 * tp)) * 48 + head * 4 + 32 + q4;
        uint4 ve = qkv4[idxe];
        uint4 vo = qkv4[idxe + 48];
        int kc = tp >> 3, kw2 = tp & 7;
        int off = (kw2 & 3) * 2 + (kw2 >> 2);
        unsigned ew[4] = {ve.x, ve.y, ve.z, ve.w};
        unsigned ow[4] = {vo.x, vo.y, vo.z, vo.w};
#pragma unroll
        for (int j = 0; j < 4; j++) {
            int wd = q4 * 4 + j;
            unsigned d0 = __byte_perm(ew[j], ow[j], 0x5410);
            unsigned d1 = __byte_perm(ew[j], ow[j], 0x7632);
            int n0 = 2 * wd, n1 = 2 * wd + 1;
            VB[(n0 >> 3) * 528 + kc * 66 + (n0 & 7) * 8 + off] = d0;
            VB[(n1 >> 3) * 528 + kc * 66 + (n1 & 7) * 8 + off] = d1;
        }
    }
    __syncthreads();

    float acc[16][4];
#pragma unroll
    for (int nt = 0; nt < 16; nt++)
#pragma unroll
        for (int i = 0; i < 4; i++) acc[nt][i] = 0.f;

#pragma unroll
    for (int k16 = 0; k16 < 2; k16++) {
        int abase = (w * 2) * 132 + k16 * 66 + lane * 2;
        uint2 q0 = *reinterpret_cast<const uint2*>(&QA[abase]);
        uint2 q1 = *reinterpret_cast<const uint2*>(&QA[abase + 132]);
#pragma unroll
        for (int nt = 0; nt < 16; nt++) {
            uint2 b = *reinterpret_cast<const uint2*>(&KB[nt * 132 + k16 * 66 + lane * 2]);
            MMA_BF16(acc[nt], q0.x, q1.x, q0.y, q1.y, b.x, b.y);
        }
    }

    const int qtile = w & 3;
    float m0 = -1e30f, m1 = -1e30f;
#pragma unroll
    for (int nt = 0; nt < 16; nt++) {
        float4 p = *reinterpret_cast<const float4*>(psh + ((qtile * 8 + (nt & 7)) * 32 + lane) * 4);
        acc[nt][0] += p.x; acc[nt][1] += p.y;
        acc[nt][2] += p.z; acc[nt][3] += p.w;
        m0 = fmaxf(m0, fmaxf(acc[nt][0], acc[nt][1]));
        m1 = fmaxf(m1, fmaxf(acc[nt][2], acc[nt][3]));
    }
    m0 = fmaxf(m0, __shfl_xor_sync(0xffffffffu, m0, 1));
    m0 = fmaxf(m0, __shfl_xor_sync(0xffffffffu, m0, 2));
    m1 = fmaxf(m1, __shfl_xor_sync(0xffffffffu, m1, 1));
    m1 = fmaxf(m1, __shfl_xor_sync(0xffffffffu, m1, 2));

    float l0 = 0.f, l1 = 0.f;
#pragma unroll
    for (int nt = 0; nt < 16; nt++) {
        acc[nt][0] = __expf(acc[nt][0] - m0);
        acc[nt][1] = __expf(acc[nt][1] - m0);
        acc[nt][2] = __expf(acc[nt][2] - m1);
        acc[nt][3] = __expf(acc[nt][3] - m1);
        l0 += acc[nt][0] + acc[nt][1];
        l1 += acc[nt][2] + acc[nt][3];
    }
    l0 += __shfl_xor_sync(0xffffffffu, l0, 1);
    l0 += __shfl_xor_sync(0xffffffffu, l0, 2);
    l1 += __shfl_xor_sync(0xffffffffu, l1, 1);
    l1 += __shfl_xor_sync(0xffffffffu, l1, 2);
    float inv0 = 1.0f / l0, inv1 = 1.0f / l1;

    float oacc[4][4];
#pragma unroll
    for (int n8 = 0; n8 < 4; n8++)
#pragma unroll
        for (int i = 0; i < 4; i++) oacc[n8][i] = 0.f;

#pragma unroll
    for (int kc = 0; kc < 8; kc++) {
        unsigned a0 = pack_bf(acc[2 * kc][0], acc[2 * kc][1]);
        unsigned a1 = pack_bf(acc[2 * kc][2], acc[2 * kc][3]);
        unsigned a2 = pack_bf(acc[2 * kc + 1][0], acc[2 * kc + 1][1]);
        unsigned a3 = pack_bf(acc[2 * kc + 1][2], acc[2 * kc + 1][3]);
#pragma unroll
        for (int n8 = 0; n8 < 4; n8++) {
            uint2 b = *reinterpret_cast<const uint2*>(&VB[n8 * 528 + kc * 66 + lane * 2]);
            MMA_BF16(oacc[n8], a0, a1, a2, a3, b.x, b.y);
        }
    }

    int r0 = win * 128 + w * 16 + g;
#pragma unroll
    for (int n8 = 0; n8 < 4; n8++) {
        int colw = head * 16 + n8 * 4 + t;
        attout[(size_t)r0 * 64 + colw]       = pack_bf(oacc[n8][0] * inv0, oacc[n8][1] * inv0);
        attout[(size_t)(r0 + 8) * 64 + colw] = pack_bf(oacc[n8][2] * inv1, oacc[n8][3] * inv1);
    }
}

// ---------------- proj (bf16) + scatter + residual + LN2, BM=64; xln packed ----------------
#define PROJ_SMEM (4224 * 4)
__global__ __launch_bounds__(256) void projln_kernel(
    const unsigned* __restrict__ attn, const unsigned* __restrict__ Wp_,
    const float* __restrict__ bias, const float* __restrict__ res,
    float* __restrict__ xres, unsigned* __restrict__ xln,
    const float* __restrict__ gw, const float* __restrict__ bw) {
    extern __shared__ unsigned sm[];
    unsigned* OA = sm;   // 8 rowgrps x 528
    __shared__ float smS[64][2], smQ[64][2];

    const int bm = blockIdx.x * 64;
    const int tid = threadIdx.x;
    const int lane = tid & 31, w = tid >> 5;
    const int g = lane >> 2, t = lane & 3;
    const int wm = w >> 1, wn = w & 1;   // 4m x 2n; warp tile m16 x n64

    const uint4* attn4 = reinterpret_cast<const uint4*>(attn);
#pragma unroll
    for (int it = 0; it < 4; it++) {
        int e = tid + it * 256;
        int row = e >> 4, q4 = e & 15;
        uint4 v = attn4[((size_t)(bm + row)) * 16 + q4];
        int base = ((row >> 4) * 2 + ((row >> 3) & 1)) * 528 + (row & 7) * 8 +
                   (q4 >> 1) * 66 + (q4 & 1);
        OA[base + 0] = v.x; OA[base + 2] = v.y; OA[base + 4] = v.z; OA[base + 6] = v.w;
    }
    __syncthreads();

    const uint2* Wp2 = reinterpret_cast<const uint2*>(Wp_);
    float acc2[8][4];
#pragma unroll
    for (int ni = 0; ni < 8; ni++)
#pragma unroll
        for (int q = 0; q < 4; q++) acc2[ni][q] = 0.f;

#pragma unroll
    for (int k16 = 0; k16 < 8; k16++) {
        int base = (wm * 2) * 528 + k16 * 66 + lane * 2;
        uint2 q0 = *reinterpret_cast<const uint2*>(&OA[base]);
        uint2 q1 = *reinterpret_cast<const uint2*>(&OA[base + 528]);
#pragma unroll
        for (int ni = 0; ni < 8; ni++) {
            uint2 b = Wp2[((wn * 8 + ni) * 8 + k16) * 32 + lane];
            MMA_BF16(acc2[ni], q0.x, q1.x, q0.y, q1.y, b.x, b.y);
        }
    }

#pragma unroll
    for (int rh = 0; rh < 2; rh++) {
        int lrow = wm * 16 + g + rh * 8;
        int xrow = perm_row(bm + lrow);
        float v[16];
        float s = 0.f, q = 0.f;
#pragma unroll
        for (int ni = 0; ni < 8; ni++) {
            int cc = wn * 64 + ni * 8 + t * 2;
            float2 rr = *reinterpret_cast<const float2*>(res + (size_t)xrow * 128 + cc);
            float x0 = acc2[ni][rh * 2 + 0] + bias[cc] + rr.x;
            float x1 = acc2[ni][rh * 2 + 1] + bias[cc + 1] + rr.y;
            *reinterpret_cast<float2*>(xres + (size_t)xrow * 128 + cc) = make_float2(x0, x1);
            v[ni * 2 + 0] = x0; v[ni * 2 + 1] = x1;
            s += x0 + x1; q += x0 * x0 + x1 * x1;
        }
        s += __shfl_xor_sync(0xffffffffu, s, 1);
        s += __shfl_xor_sync(0xffffffffu, s, 2);
        q += __shfl_xor_sync(0xffffffffu, q, 1);
        q += __shfl_xor_sync(0xffffffffu, q, 2);
        if (t == 0) { smS[lrow][wn] = s; smQ[lrow][wn] = q; }
        __syncthreads();
        float S = smS[lrow][0] + smS[lrow][1];
        float Q = smQ[lrow][0] + smQ[lrow][1];
        float mu = S * (1.f / 128.f);
        float var = Q * (1.f / 128.f) - mu * mu;
        float rs = rsqrtf(var + 1e-5f);
#pragma unroll
        for (int ni = 0; ni < 8; ni++) {
            int cc = wn * 64 + ni * 8 + t * 2;
            xln[(size_t)xrow * 64 + (cc >> 1)] =
                pack_bf((v[ni * 2 + 0] - mu) * rs * gw[cc] + bw[cc],
                        (v[ni * 2 + 1] - mu) * rs * gw[cc + 1] + bw[cc + 1]);
        }
    }
}

// ---------------- fused MLP (bf16, reg-direct handoff, packed xln input) ----------------
#define MLP_SMEM (21120 * 4)
__global__ void __launch_bounds__(256, 2) mlp_kernel(
    const unsigned* __restrict__ xln, const unsigned* __restrict__ W1g4_,
    const unsigned* __restrict__ W2g4_,
    const float* __restrict__ b1, const float* __restrict__ b2,
    const float* __restrict__ res, float* __restrict__ out,
    const float* __restrict__ gw, const float* __restrict__ bw) {
    extern __shared__ unsigned sm[];
    unsigned* XA = sm;
    unsigned* W1 = sm + 8448;
    unsigned* W2 = sm + 16896;

    const uint4* W1g = reinterpret_cast<const uint4*>(W1g4_);
    const uint4* W2g = reinterpret_cast<const uint4*>(W2g4_);

    const int tid = threadIdx.x;
    const int lane = tid & 31;
    const int w = tid >> 5;
    const int g = lane >> 2, t = lane & 3;
    const int bm = blockIdx.x * 128;

    // stage XA: raw packed uint4 copy, 128 rows x 16 uint4
    const uint4* xln4 = reinterpret_cast<const uint4*>(xln);
#pragma unroll
    for (int it = 0; it < 8; it++) {
        int e = tid + it * 256;
        int row = e >> 4, q4 = e & 15;
        uint4 v = xln4[((size_t)(bm + row)) * 16 + q4];
        int base = ((row >> 4) * 2 + ((row >> 3) & 1)) * 528 + (row & 7) * 8 +
                   (q4 >> 1) * 66 + (q4 & 1);
        XA[base + 0] = v.x; XA[base + 2] = v.y; XA[base + 4] = v.z; XA[base + 6] = v.w;
    }

    int w1src[4], w1st[4], w2src[4], w2st[4];
#pragma unroll
    for (int it = 0; it < 4; it++) {
        int e = tid + it * 256;
        int n = e >> 4, wq = e & 15;
        w1src[it] = n * 16 + wq;
        w1st[it] = (n >> 3) * 528 + (wq >> 1) * 66 + (n & 7) * 8 + (wq & 1);
        int n2 = e >> 3, wq2 = e & 7;
        w2src[it] = n2 * 64 + wq2;
        w2st[it] = (n2 >> 3) * 264 + (wq2 >> 1) * 66 + (n2 & 7) * 8 + (wq2 & 1);
    }

    {
        uint4 v[4];
#pragma unroll
        for (int it = 0; it < 4; it++) v[it] = W1g[w1src[it]];
#pragma unroll
        for (int it = 0; it < 4; it++) {
            W1[w1st[it] + 0] = v[it].x; W1[w1st[it] + 2] = v[it].y;
            W1[w1st[it] + 4] = v[it].z; W1[w1st[it] + 6] = v[it].w;
        }
    }
    __syncthreads();

    float acco[16][4];
#pragma unroll
    for (int ni = 0; ni < 16; ni++)
#pragma unroll
        for (int q = 0; q < 4; q++) acco[ni][q] = 0.f;

    int p = 0;
    for (int c = 0; c < 8; c++) {
        uint4 w2v[4];
#pragma unroll
        for (int it = 0; it < 4; it++) w2v[it] = W2g[w2src[it] + c * 8];

        float accs[8][4];
#pragma unroll
        for (int ni = 0; ni < 8; ni++)
#pragma unroll
            for (int q = 0; q < 4; q++) accs[ni][q] = 0.f;

        unsigned* W1p = W1 + p * 4224;
#pragma unroll
        for (int k16 = 0; k16 < 8; k16++) {
            int abase = (w * 2) * 528 + k16 * 66 + lane * 2;
            uint2 q0 = *reinterpret_cast<const uint2*>(&XA[abase]);
            uint2 q1 = *reinterpret_cast<const uint2*>(&XA[abase + 528]);
#pragma unroll
            for (int ni = 0; ni < 8; ni++) {
                uint2 b = *reinterpret_cast<const uint2*>(&W1p[ni * 528 + k16 * 66 + lane * 2]);
                MMA_BF16(accs[ni], q0.x, q1.x, q0.y, q1.y, b.x, b.y);
            }
        }

#pragma unroll
        for (int it = 0; it < 4; it++) {
            W2[w2st[it] + 0] = w2v[it].x; W2[w2st[it] + 2] = w2v[it].y;
            W2[w2st[it] + 4] = w2v[it].z; W2[w2st[it] + 6] = w2v[it].w;
        }

        unsigned aw[4][4];
#pragma unroll
        for (int ni = 0; ni < 8; ni++) {
            int kl = c * 64 + ni * 8 + t * 2;
            float bb0 = b1[kl], bb1 = b1[kl + 1];
            float x0 = accs[ni][0] + bb0;
            float x1 = accs[ni][1] + bb1;
            float x2 = accs[ni][2] + bb0;
            float x3 = accs[ni][3] + bb1;
            x0 = 0.5f * x0 * (1.0f + erff(x0 * 0.7071067811865475f));
            x1 = 0.5f * x1 * (1.0f + erff(x1 * 0.7071067811865475f));
            x2 = 0.5f * x2 * (1.0f + erff(x2 * 0.7071067811865475f));
            x3 = 0.5f * x3 * (1.0f + erff(x3 * 0.7071067811865475f));
            int kc = ni >> 1;
            if ((ni & 1) == 0) {
                aw[kc][0] = pack_bf(x0, x1);
                aw[kc][1] = pack_bf(x2, x3);
            } else {
                aw[kc][2] = pack_bf(x0, x1);
                aw[kc][3] = pack_bf(x2, x3);
            }
        }
        __syncthreads();

        uint4 w1v[4];
        if (c < 7) {
#pragma unroll
            for (int it = 0; it < 4; it++) w1v[it] = W1g[w1src[it] + (c + 1) * 1024];
        }

#pragma unroll
        for (int kc = 0; kc < 4; kc++) {
#pragma unroll
            for (int ni = 0; ni < 16; ni++) {
                uint2 b = *reinterpret_cast<const uint2*>(&W2[ni * 264 + kc * 66 + lane * 2]);
                MMA_BF16(acco[ni], aw[kc][0], aw[kc][1], aw[kc][2], aw[kc][3], b.x, b.y);
            }
        }

        if (c < 7) {
            unsigned* Wn = W1 + (p ^ 1) * 4224;
#pragma unroll
            for (int it = 0; it < 4; it++) {
                Wn[w1st[it] + 0] = w1v[it].x; Wn[w1st[it] + 2] = w1v[it].y;
                Wn[w1st[it] + 4] = w1v[it].z; Wn[w1st[it] + 6] = w1v[it].w;
            }
            p ^= 1;
        }
        __syncthreads();
    }

#pragma unroll
    for (int rh = 0; rh < 2; rh++) {
        int r = bm + w * 16 + g + rh * 8;
        float v[32];
        float s = 0.f, q = 0.f;
#pragma unroll
        for (int ni = 0; ni < 16; ni++) {
            int cc = ni * 8 + t * 2;
            float2 rr = *reinterpret_cast<const float2*>(res + (size_t)r * 128 + cc);
            float x0 = acco[ni][rh * 2 + 0] + b2[cc] + rr.x;
            float x1 = acco[ni][rh * 2 + 1] + b2[cc + 1] + rr.y;
            v[ni * 2 + 0] = x0; v[ni * 2 + 1] = x1;
            s += x0 + x1; q += x0 * x0 + x1 * x1;
        }
        s += __shfl_xor_sync(0xffffffffu, s, 1);
        s += __shfl_xor_sync(0xffffffffu, s, 2);
        q += __shfl_xor_sync(0xffffffffu, q, 1);
        q += __shfl_xor_sync(0xffffffffu, q, 2);
        float mu = s * (1.f / 128.f);
        float var = q * (1.f / 128.f) - mu * mu;
        float rs = rsqrtf(var + 1e-5f);
#pragma unroll
        for (int ni = 0; ni < 16; ni++) {
            int cc = ni * 8 + t * 2;
            float2 o;
            o.x = (v[ni * 2 + 0] - mu) * rs * gw[cc] + bw[cc];
            o.y = (v[ni * 2 + 1] - mu) * rs * gw[cc + 1] + bw[cc + 1];
            *reinterpret_cast<float2*>(out + (size_t)r * 128 + cc) = o;
        }
    }
}

// ---------------- launch ----------------
extern "C" void kernel_launch(void* const* d_in, const int* in_sizes, int n_in,
                              void* d_out, int out_size) {
    const float* x_v    = (const float*)d_in[0];
    const float* qkv_w  = (const float*)d_in[1];
    const float* qkv_b  = (const float*)d_in[2];
    const float* proj_w = (const float*)d_in[3];
    const float* proj_b = (const float*)d_in[4];
    const float* rpb    = (const float*)d_in[5];
    const float* n1w    = (const float*)d_in[6];
    const float* n1b    = (const float*)d_in[7];
    const float* n2w    = (const float*)d_in[8];
    const float* n2b    = (const float*)d_in[9];
    const float* fc1w   = (const float*)d_in[10];
    const float* fc1b   = (const float*)d_in[11];
    const float* fc2w   = (const float*)d_in[12];
    const float* fc2b   = (const float*)d_in[13];
    float* out = (float*)d_out;

    float *xres, *ps;
    unsigned *qkvb, *attn, *xln, *wtf;
    cudaGetSymbolAddress((void**)&qkvb, g_qkv);
    cudaGetSymbolAddress((void**)&attn, g_attn);
    cudaGetSymbolAddress((void**)&xln,  g_xln);
    cudaGetSymbolAddress((void**)&xres, g_xres);
    cudaGetSymbolAddress((void**)&ps,   g_ps);
    cudaGetSymbolAddress((void**)&wtf,  g_wtf);

    cudaFuncSetAttribute(qkv_kernel, cudaFuncAttributeMaxDynamicSharedMemorySize, QKV_SMEM);
    cudaFuncSetAttribute(attn_kernel, cudaFuncAttributeMaxDynamicSharedMemorySize, SMEM_ATTN);
    cudaFuncSetAttribute(projln_kernel, cudaFuncAttributeMaxDynamicSharedMemorySize, PROJ_SMEM);
    cudaFuncSetAttribute(mlp_kernel, cudaFuncAttributeMaxDynamicSharedMemorySize, MLP_SMEM);

    // 0. setup: weights (bf16 packed) + rpb/mask table
    setup_kernel<<<1408, 256>>>(qkv_w, proj_w, fc1w, fc2w, rpb, wtf, ps);
    // 1. qkv (bf16), packed bf16x2 output
    qkv_kernel<<<1024, 512, QKV_SMEM>>>(x_v, wtf, qkv_b, qkvb);
    // 2. window attention (all bf16)
    attn_kernel<<<dim3(1024, HEADS), 256, SMEM_ATTN>>>(qkvb, ps, attn);
    // 3. proj (bf16) + scatter + residual + LN2 (xln packed bf16)
    projln_kernel<<<2048, 256, PROJ_SMEM>>>(attn, wtf + 24576, proj_b,
                                            x_v, xres, xln, n2w, n2b);
    // 4. fused MLP (bf16, reg handoff, packed input) -> final output
    mlp_kernel<<<1024, 256, MLP_SMEM>>>(xln, wtf + 32768, wtf + 65536,
                                        fc1b, fc2b, xres, out, n1w, n1b);
}